// round 13
// baseline (speedup 1.0000x reference)
#include <cuda_runtime.h>
#include <cuda_fp16.h>
#include <cstdint>

#define DIM 1536
#define HEADS 12
#define HD 128
#define NQ 16384
#define HALF (NQ / 2)
#define IMG 257
#define TXT 512
#define IMGP 320   // img rows padded to multiple of 64

typedef __half h16;

// ---------------- scratch (no allocations allowed) ----------------
__device__ float g_Q[(long)NQ * DIM];
__device__ float g_O[(long)NQ * DIM];          // attention partial (txt segment)
__device__ float g_K[(long)TXT * DIM];
__device__ float g_V[(long)TXT * DIM];
__device__ float g_Ki[(long)IMG * DIM];
__device__ float g_Vi[(long)IMG * DIM];
__device__ h16 g_xh[(long)NQ * DIM];
__device__ h16 g_Qh[(long)NQ * DIM];
__device__ h16 g_Oh[(long)NQ * DIM];
__device__ h16 g_Kh[(long)TXT * DIM];
__device__ h16 g_Vh[(long)TXT * DIM];
__device__ h16 g_Kih[(long)IMGP * DIM];
__device__ h16 g_Vih[(long)IMGP * DIM];
__device__ h16 g_WqT[(long)DIM * DIM];
__device__ h16 g_WoT[(long)DIM * DIM];

// ---------------- PTX helpers ----------------
__device__ __forceinline__ uint32_t s2u(const void* p) {
    return (uint32_t)__cvta_generic_to_shared(p);
}
__device__ __forceinline__ void cp16(uint32_t s, const void* g) {
    asm volatile("cp.async.cg.shared.global [%0], [%1], 16;\n" :: "r"(s), "l"(g) : "memory");
}
__device__ __forceinline__ void cp_commit() {
    asm volatile("cp.async.commit_group;\n" ::: "memory");
}
template <int N>
__device__ __forceinline__ void cp_wait() {
    asm volatile("cp.async.wait_group %0;\n" :: "n"(N) : "memory");
}
__device__ __forceinline__ void ldsm4(uint32_t* r, uint32_t a) {
    asm volatile("ldmatrix.sync.aligned.m8n8.x4.shared.b16 {%0,%1,%2,%3}, [%4];"
                 : "=r"(r[0]), "=r"(r[1]), "=r"(r[2]), "=r"(r[3]) : "r"(a));
}
__device__ __forceinline__ void ldsm4t(uint32_t* r, uint32_t a) {
    asm volatile("ldmatrix.sync.aligned.m8n8.x4.trans.shared.b16 {%0,%1,%2,%3}, [%4];"
                 : "=r"(r[0]), "=r"(r[1]), "=r"(r[2]), "=r"(r[3]) : "r"(a));
}
__device__ __forceinline__ void mma16816(float* c, const uint32_t* a, const uint32_t* b) {
    asm volatile(
        "mma.sync.aligned.m16n8k16.row.col.f32.f16.f16.f32 "
        "{%0,%1,%2,%3}, {%4,%5,%6,%7}, {%8,%9}, {%0,%1,%2,%3};"
        : "+f"(c[0]), "+f"(c[1]), "+f"(c[2]), "+f"(c[3])
        : "r"(a[0]), "r"(a[1]), "r"(a[2]), "r"(a[3]), "r"(b[0]), "r"(b[1]));
}
__device__ __forceinline__ uint32_t packh(float a, float b) {
    __half2 t = __floats2half2_rn(a, b);
    return *(uint32_t*)&t;
}
__device__ __forceinline__ float ex2(float x) {
    float y;
    asm("ex2.approx.ftz.f32 %0, %1;" : "=f"(y) : "f"(x));
    return y;
}

// ---------------- single-pass fp16 HMMA GEMM: C = A @ BT^T + bias ----------------
#define GSTRIDE 80
#define TILE_B (128 * GSTRIDE)
#define STAGE_B (2 * TILE_B)   // A, B
#define NSTAGE 4

__global__ __launch_bounds__(256, 2)
void gemm_mma_f16(const h16* __restrict__ A, const h16* __restrict__ BT,
                  const float* __restrict__ bias, float* __restrict__ C) {
    extern __shared__ char dynsm[];
    const uint32_t smem0 = s2u(dynsm);
    const int tid = threadIdx.x;
    const int lane = tid & 31;
    const int wid = tid >> 5;
    const int wm = wid & 3;
    const int wn = wid >> 2;
    const int m0 = blockIdx.y * 128;
    const int n0 = blockIdx.x * 128;

    const h16* srcs[2] = {A, BT};
    const int bases[2] = {m0, n0};

    auto load_stage = [&](int slot, int k0) {
        const uint32_t sb = smem0 + slot * STAGE_B;
#pragma unroll
        for (int t = 0; t < 4; ++t) {
            const int ch = tid + t * 256;      // 1024 chunks
            const int tile = ch >> 9;
            const int idx = ch & 511;
            const int row = idx >> 2;
            const int cb = idx & 3;
            const uint32_t so = sb + tile * TILE_B + row * GSTRIDE + cb * 16;
            const h16* g = srcs[tile] + (size_t)(bases[tile] + row) * DIM + k0 + cb * 8;
            cp16(so, g);
        }
        cp_commit();
    };

    for (int s = 0; s < NSTAGE; ++s) load_stage(s, s * 32);

    float acc[2][8][4];
#pragma unroll
    for (int mi = 0; mi < 2; ++mi)
#pragma unroll
        for (int nj = 0; nj < 8; ++nj)
#pragma unroll
            for (int r = 0; r < 4; ++r) acc[mi][nj][r] = 0.f;

    const int rowA = wm * 32 + (lane & 15);
    const int acol = (lane >> 4) * 16;
    const int rowB = wn * 64 + (lane >> 4) * 8 + (lane & 7);
    const int bcol = ((lane >> 3) & 1) * 16;

    constexpr int NKC = DIM / 32;
    for (int i = 0; i < NKC; ++i) {
        const int slot = i % NSTAGE;
        const uint32_t sb = smem0 + slot * STAGE_B;
        cp_wait<NSTAGE - 1>();
        __syncthreads();

        const uint32_t aA = sb + rowA * GSTRIDE + acol;
        const uint32_t aB = sb + TILE_B + rowB * GSTRIDE + bcol;

        // fragment burst: load everything for the chunk, then MMA burst
        uint32_t ah[2][2][4], bh[2][4][4];
#pragma unroll
        for (int k16 = 0; k16 < 2; ++k16) {
            const uint32_t ko = k16 * 32;
#pragma unroll
            for (int mi = 0; mi < 2; ++mi)
                ldsm4(ah[k16][mi], aA + mi * 16 * GSTRIDE + ko);
#pragma unroll
            for (int ni = 0; ni < 4; ++ni)
                ldsm4(bh[k16][ni], aB + ni * 16 * GSTRIDE + ko);
        }
#pragma unroll
        for (int k16 = 0; k16 < 2; ++k16)
#pragma unroll
            for (int mi = 0; mi < 2; ++mi)
#pragma unroll
                for (int nj = 0; nj < 8; ++nj)
                    mma16816(acc[mi][nj], ah[k16][mi], &bh[k16][nj >> 1][(nj & 1) * 2]);

        __syncthreads();
        if (i + NSTAGE < NKC) load_stage(slot, (i + NSTAGE) * 32);
        else cp_commit();
    }

    const int crow0 = m0 + wm * 32 + (lane >> 2);
    const int ccol0 = n0 + wn * 64 + (lane & 3) * 2;
#pragma unroll
    for (int nj = 0; nj < 8; ++nj) {
        const int col = ccol0 + nj * 8;
        const float b0 = bias[col], b1 = bias[col + 1];
#pragma unroll
        for (int mi = 0; mi < 2; ++mi) {
            float* c0 = C + (size_t)(crow0 + mi * 16) * DIM + col;
            float* c1 = c0 + 8 * DIM;
            *(float2*)c0 = make_float2(acc[mi][nj][0] + b0, acc[mi][nj][1] + b1);
            *(float2*)c1 = make_float2(acc[mi][nj][2] + b0, acc[mi][nj][3] + b1);
        }
    }
}

// ---------------- flat fp32 -> fp16 convert ----------------
__global__ __launch_bounds__(256)
void tohalf_flat(const float* __restrict__ X, h16* __restrict__ H, long n4) {
    long i = ((long)blockIdx.x * 256 + threadIdx.x);
    if (i >= n4) return;
    float4 v = *((const float4*)X + i);
    __half2* Hp = (__half2*)H + i * 2;
    Hp[0] = __floats2half2_rn(v.x, v.y);
    Hp[1] = __floats2half2_rn(v.z, v.w);
}

// ---------------- transpose weights to single fp16 ----------------
__global__ __launch_bounds__(256)
void wT_kernel(const float* __restrict__ W, h16* __restrict__ Ht) {
    __shared__ float t[32][33];
    const int k0 = blockIdx.y * 32, n0 = blockIdx.x * 32;
    const int tx = threadIdx.x, ty = threadIdx.y;
#pragma unroll
    for (int j = 0; j < 4; ++j)
        t[ty + j * 8][tx] = W[(size_t)(k0 + ty + j * 8) * DIM + n0 + tx];
    __syncthreads();
#pragma unroll
    for (int j = 0; j < 4; ++j)
        Ht[(size_t)(n0 + ty + j * 8) * DIM + k0 + tx] = __float2half(t[tx][ty + j * 8]);
}

// ---------------- small fused SGEMM ----------------
struct SmallJobs {
    const float* A[4];
    const float* W[4];
    const float* b[4];
    float* C[4];
    int M[4];
};

__global__ __launch_bounds__(256)
void sgemm_small(SmallJobs jobs) {
    const int z = blockIdx.z;
    const float* A = jobs.A[z];
    const float* B = jobs.W[z];
    const float* bias = jobs.b[z];
    float* C = jobs.C[z];
    const int M = jobs.M[z];
    const int N = DIM, K = DIM;

    const int m0 = blockIdx.y * 128;
    if (m0 >= M) return;
    const int n0 = blockIdx.x * 64;

    __shared__ float As[16 * 132];
    __shared__ float Bs[16 * 64];
    const int tid = threadIdx.x;
    const int tx = tid & 15;
    const int ty = tid >> 4;
    const int arow = tid >> 1;
    const int ak = (tid & 1) * 8;
    const int brow = tid >> 4;
    const int bcol = (tid & 15) * 4;

    float acc[8][4];
#pragma unroll
    for (int i = 0; i < 8; ++i)
#pragma unroll
        for (int j = 0; j < 4; ++j) acc[i][j] = 0.f;

    const bool avalid = (m0 + arow) < M;
    const float* Aptr = A + (long)(m0 + arow) * K + ak;
    const float* Bptr = B + (long)brow * N + n0 + bcol;

    for (int k0 = 0; k0 < K; k0 += 16) {
        float4 a0 = make_float4(0.f, 0.f, 0.f, 0.f);
        float4 a1 = make_float4(0.f, 0.f, 0.f, 0.f);
        if (avalid) {
            a0 = *(const float4*)(Aptr + k0);
            a1 = *(const float4*)(Aptr + k0 + 4);
        }
        As[(ak + 0) * 132 + arow] = a0.x;
        As[(ak + 1) * 132 + arow] = a0.y;
        As[(ak + 2) * 132 + arow] = a0.z;
        As[(ak + 3) * 132 + arow] = a0.w;
        As[(ak + 4) * 132 + arow] = a1.x;
        As[(ak + 5) * 132 + arow] = a1.y;
        As[(ak + 6) * 132 + arow] = a1.z;
        As[(ak + 7) * 132 + arow] = a1.w;
        *(float4*)(Bs + brow * 64 + bcol) = *(const float4*)(Bptr + (long)k0 * N);
        __syncthreads();
#pragma unroll
        for (int kk = 0; kk < 16; ++kk) {
            float4 x0 = *(const float4*)(As + kk * 132 + ty * 8);
            float4 x1 = *(const float4*)(As + kk * 132 + ty * 8 + 4);
            float4 y = *(const float4*)(Bs + kk * 64 + tx * 4);
            float a[8] = {x0.x, x0.y, x0.z, x0.w, x1.x, x1.y, x1.z, x1.w};
            float b[4] = {y.x, y.y, y.z, y.w};
#pragma unroll
            for (int i = 0; i < 8; ++i)
#pragma unroll
                for (int j = 0; j < 4; ++j) acc[i][j] += a[i] * b[j];
        }
        __syncthreads();
    }

    float4 bv = *(const float4*)(bias + n0 + tx * 4);
    float bb[4] = {bv.x, bv.y, bv.z, bv.w};
#pragma unroll
    for (int i = 0; i < 8; ++i) {
        int m = m0 + ty * 8 + i;
        if (m < M) {
            float4 out;
            out.x = acc[i][0] + bb[0];
            out.y = acc[i][1] + bb[1];
            out.z = acc[i][2] + bb[2];
            out.w = acc[i][3] + bb[3];
            *(float4*)(C + (long)m * N + n0 + tx * 4) = out;
        }
    }
}

// ---------------- RMSNorm -> single fp16 (optional scale), zero-pad ----------------
__global__ __launch_bounds__(256)
void rmsnorm_single(const float* __restrict__ X, const float* __restrict__ g, float scale,
                    h16* __restrict__ H, int nvalid) {
    const int r = blockIdx.x;
    const int tid = threadIdx.x;
    if (r >= nvalid) {
#pragma unroll
        for (int i = 0; i < 6; ++i)
            H[(long)r * DIM + tid + i * 256] = __float2half(0.f);
        return;
    }
    const float* x = X + (long)r * DIM;
    float v[6];
    float ss = 0.f;
#pragma unroll
    for (int i = 0; i < 6; ++i) {
        v[i] = x[tid + i * 256];
        ss += v[i] * v[i];
    }
#pragma unroll
    for (int off = 16; off >= 1; off >>= 1)
        ss += __shfl_xor_sync(0xffffffffu, ss, off);
    __shared__ float red[8];
    if ((tid & 31) == 0) red[tid >> 5] = ss;
    __syncthreads();
    float tot = 0.f;
#pragma unroll
    for (int i = 0; i < 8; ++i) tot += red[i];
    const float rms = rsqrtf(tot * (1.f / (float)DIM) + 1e-6f);
#pragma unroll
    for (int i = 0; i < 6; ++i)
        H[(long)r * DIM + tid + i * 256] = __float2half(v[i] * rms * g[tid + i * 256] * scale);
}

// ---------------- fp16 (single) row convert with zero-pad ----------------
__global__ __launch_bounds__(256)
void tohalf_pad(const float* __restrict__ X, h16* __restrict__ H, int nvalid) {
    const int r = blockIdx.x;
    const int tid = threadIdx.x;
#pragma unroll
    for (int i = 0; i < 6; ++i) {
        float val = (r < nvalid) ? X[(long)r * DIM + tid + i * 256] : 0.f;
        H[(long)r * DIM + tid + i * 256] = __float2half(val);
    }
}

// ---------------- HMMA flash attention ----------------
// Single-pass fp16 QK and PV; exp2-domain softmax; KV double-buffered; 2 CTAs/SM.
#define AST 272            // smem row stride bytes (128 fp16 + 16B pad)
#define KVROW (64 * AST)
#define KVST (2 * KVROW)   // Kh, Vh per stage

__global__ __launch_bounds__(256, 2)
void attn_mma(int qb0) {
    extern __shared__ char smem[];
    const uint32_t sQh = s2u(smem);
    const uint32_t sKV = sQh + 128 * AST;   // 2 stages of KVST

    const int tid = threadIdx.x, lane = tid & 31, wid = tid >> 5;
    const int qb = blockIdx.x + qb0, h = blockIdx.y;
    const long qrow0 = (long)qb * 128;

    // Q load (its own commit group)
    {
        const h16* Qhg = g_Qh + qrow0 * DIM + h * HD;
#pragma unroll
        for (int t = 0; t < 8; ++t) {
            int c = tid + t * 256;
            int r = c >> 4, cb = c & 15;
            cp16(sQh + r * AST + cb * 16, Qhg + (long)r * DIM + cb * 8);
        }
        cp_commit();
    }

    const uint32_t qoff = (uint32_t)((wid * 16 + (lane & 15)) * AST + (lane >> 4) * 16);
    const uint32_t koff = (uint32_t)((((lane >> 4) << 3) + (lane & 7)) * AST + ((lane >> 3) & 1) * 16);
    const uint32_t voff = (uint32_t)(((((lane >> 3) & 1) << 3) + (lane & 7)) * AST + (lane >> 4) * 16);

    const int r0 = lane >> 2;
    const int colb = (lane & 3) * 2;

#pragma unroll 1
    for (int seg = 0; seg < 2; ++seg) {
        const h16 *Khg, *Vhg;
        int len, ntiles;
        if (seg == 0) {
            Khg = g_Kh; Vhg = g_Vh;
            len = TXT; ntiles = TXT / 64;
        } else {
            Khg = g_Kih; Vhg = g_Vih;
            len = IMG; ntiles = IMGP / 64;
        }

        auto load_kv = [&](int stage, int t) {
            const uint32_t sb = sKV + stage * KVST;
            const long kvbase = (long)t * 64 * DIM + h * HD;
            const h16* arrs[2] = {Khg, Vhg};
#pragma unroll
            for (int tt = 0; tt < 8; ++tt) {
                int c = tid + tt * 256;       // 2048 chunks
                int arr = c >> 10;
                int idx = c & 1023;
                int r = idx >> 4, cb = idx & 15;
                cp16(sb + arr * KVROW + r * AST + cb * 16,
                     arrs[arr] + kvbase + (long)r * DIM + cb * 8);
            }
            cp_commit();
        };

        load_kv(0, 0);  // prologue

        float mrow0 = -1e30f, mrow1 = -1e30f, lsum0 = 0.f, lsum1 = 0.f;
        float O[16][4];
#pragma unroll
        for (int j = 0; j < 16; ++j)
#pragma unroll
            for (int e = 0; e < 4; ++e) O[j][e] = 0.f;

#pragma unroll 1
        for (int t = 0; t < ntiles; ++t) {
            __syncthreads();   // all warps finished reading buffer (t+1)&1 (from iter t-1)
            if (t + 1 < ntiles) {
                load_kv((t + 1) & 1, t + 1);
                cp_wait<1>();
            } else {
                cp_wait<0>();
            }
            __syncthreads();   // buffer t&1 visible to all

            const uint32_t sb = sKV + (t & 1) * KVST;
            const uint32_t sKh_ = sb, sVh_ = sb + KVROW;

            // ---- S = Q K^T (single fp16 pass, log2-domain logits) ----
            float S[8][4];
#pragma unroll
            for (int j = 0; j < 8; ++j)
#pragma unroll
                for (int e = 0; e < 4; ++e) S[j][e] = 0.f;
#pragma unroll
            for (int k16 = 0; k16 < 8; ++k16) {
                uint32_t ah[4], bh[4][4];
                ldsm4(ah, sQh + qoff + k16 * 32);
#pragma unroll
                for (int nt2 = 0; nt2 < 4; ++nt2)
                    ldsm4(bh[nt2], sKh_ + koff + nt2 * 16 * AST + k16 * 32);
#pragma unroll
                for (int nt2 = 0; nt2 < 4; ++nt2) {
                    mma16816(S[2 * nt2], ah, bh[nt2]);
                    mma16816(S[2 * nt2 + 1], ah, bh[nt2] + 2);
                }
            }

            // ---- online softmax (base-2) ----
            const int t0 = t * 64;
            if (t0 + 64 > len) {
#pragma unroll
                for (int j = 0; j < 8; ++j) {
#pragma unroll
                    for (int e = 0; e < 2; ++e) {
                        if (t0 + j * 8 + colb + e >= len) {
                            S[j][e] = -1e30f;
                            S[j][2 + e] = -1e30f;
                        }
                    }
                }
            }
            float mx0 = -1e30f, mx1 = -1e30f;
#pragma unroll
            for (int j = 0; j < 8; ++j) {
                mx0 = fmaxf(mx0, fmaxf(S[j][0], S[j][1]));
                mx1 = fmaxf(mx1, fmaxf(S[j][2], S[j][3]));
            }
            mx0 = fmaxf(mx0, __shfl_xor_sync(0xffffffffu, mx0, 1));
            mx0 = fmaxf(mx0, __shfl_xor_sync(0xffffffffu, mx0, 2));
            mx1 = fmaxf(mx1, __shfl_xor_sync(0xffffffffu, mx1, 1));
            mx1 = fmaxf(mx1, __shfl_xor_sync(0xffffffffu, mx1, 2));
            const float nm0 = fmaxf(mrow0, mx0);
            const float nm1 = fmaxf(mrow1, mx1);
            const float sc0 = ex2(mrow0 - nm0);
            const float sc1 = ex2(mrow1 - nm1);
            mrow0 = nm0; mrow1 = nm1;

            uint32_t Ph[8][2];
            float rs0 = 0.f, rs1 = 0.f;
#pragma unroll
            for (int j = 0; j < 8; ++j) {
                float p0 = ex2(S[j][0] - nm0);
                float p1 = ex2(S[j][1] - nm0);
                float p2 = ex2(S[j][2] - nm1);
                float p3 = ex2(S[j][3] - nm1);
                rs0 += p0 + p1;
                rs1 += p2 + p3;
                Ph[j][0] = packh(p0, p1);
                Ph[j][1] = packh(p2, p3);
            }
            rs0 += __shfl_xor_sync(0xffffffffu, rs0, 1);
            rs0 += __shfl_xor_sync(0xffffffffu, rs0, 2);
            rs1 += __shfl_xor_sync(0xffffffffu, rs1, 1);
            rs1 += __shfl_xor_sync(0xffffffffu, rs1, 2);
            lsum0 = lsum0 * sc0 + rs0;
            lsum1 = lsum1 * sc1 + rs1;
#pragma unroll
            for (int j = 0; j < 16; ++j) {
                O[j][0] *= sc0; O[j][1] *= sc0;
                O[j][2] *= sc1; O[j][3] *= sc1;
            }

            // ---- O += P V (single pass) ----
#pragma unroll
            for (int s = 0; s < 4; ++s) {
                uint32_t pah[4] = {Ph[2 * s][0], Ph[2 * s][1], Ph[2 * s + 1][0], Ph[2 * s + 1][1]};
#pragma unroll
                for (int d2 = 0; d2 < 8; ++d2) {
                    uint32_t vh[4];
                    ldsm4t(vh, sVh_ + voff + s * 16 * AST + d2 * 32);
                    mma16816(O[2 * d2], pah, vh);
                    mma16816(O[2 * d2 + 1], pah, vh + 2);
                }
            }
        }

        const float inv0 = 1.f / lsum0;
        const float inv1 = 1.f / lsum1;
        const long grow0 = qrow0 + wid * 16 + r0;
        const long grow1 = grow0 + 8;
        if (seg == 0) {
#pragma unroll
            for (int j = 0; j < 16; ++j) {
                const int d = h * HD + j * 8 + colb;
                *(float2*)(g_O + grow0 * DIM + d) = make_float2(O[j][0] * inv0, O[j][1] * inv0);
                *(float2*)(g_O + grow1 * DIM + d) = make_float2(O[j][2] * inv1, O[j][3] * inv1);
            }
        } else {
#pragma unroll
            for (int j = 0; j < 16; ++j) {
                const int d = h * HD + j * 8 + colb;
                float2 p0 = *(float2*)(g_O + grow0 * DIM + d);
                float2 p1 = *(float2*)(g_O + grow1 * DIM + d);
                *(__half2*)(g_Oh + grow0 * DIM + d) =
                    __floats2half2_rn(p0.x + O[j][0] * inv0, p0.y + O[j][1] * inv0);
                *(__half2*)(g_Oh + grow1 * DIM + d) =
                    __floats2half2_rn(p1.x + O[j][2] * inv1, p1.y + O[j][3] * inv1);
            }
        }
    }
}

// ---------------- launch ----------------
extern "C" void kernel_launch(void* const* d_in, const int* in_sizes, int n_in,
                              void* d_out, int out_size) {
    const float* x       = (const float*)d_in[0];
    const float* context = (const float*)d_in[1];
    const float* Wq  = (const float*)d_in[3];
    const float* bq  = (const float*)d_in[4];
    const float* Wk  = (const float*)d_in[5];
    const float* bk  = (const float*)d_in[6];
    const float* Wv  = (const float*)d_in[7];
    const float* bv  = (const float*)d_in[8];
    const float* Wak = (const float*)d_in[9];
    const float* bak = (const float*)d_in[10];
    const float* Wav = (const float*)d_in[11];
    const float* bav = (const float*)d_in[12];
    const float* Wo  = (const float*)d_in[13];
    const float* bo  = (const float*)d_in[14];
    const float* gq  = (const float*)d_in[15];
    const float* gk  = (const float*)d_in[16];
    const float* gak = (const float*)d_in[17];
    float* out = (float*)d_out;

    float *Qp, *Kp, *Vp, *Kip, *Vip;
    h16 *xh, *Oh, *WqT, *WoT;
    h16 *Qh, *Kh, *Vh, *Kih, *Vih;
    cudaGetSymbolAddress((void**)&Qp, g_Q);
    cudaGetSymbolAddress((void**)&Kp, g_K);
    cudaGetSymbolAddress((void**)&Vp, g_V);
    cudaGetSymbolAddress((void**)&Kip, g_Ki);
    cudaGetSymbolAddress((void**)&Vip, g_Vi);
    cudaGetSymbolAddress((void**)&xh, g_xh);
    cudaGetSymbolAddress((void**)&Oh, g_Oh);
    cudaGetSymbolAddress((void**)&WqT, g_WqT);
    cudaGetSymbolAddress((void**)&WoT, g_WoT);
    cudaGetSymbolAddress((void**)&Qh, g_Qh);
    cudaGetSymbolAddress((void**)&Kh, g_Kh);
    cudaGetSymbolAddress((void**)&Vh, g_Vh);
    cudaGetSymbolAddress((void**)&Kih, g_Kih);
    cudaGetSymbolAddress((void**)&Vih, g_Vih);

    const float* ctx_img = context;
    const float* ctx_txt = context + (long)IMG * DIM;

    static cudaStream_t s1 = nullptr, s2 = nullptr;
    static cudaEvent_t evFork = nullptr, evKV = nullptr, evA = nullptr, evS1 = nullptr;
    if (s1 == nullptr) {
        cudaStreamCreateWithFlags(&s1, cudaStreamNonBlocking);
        cudaStreamCreateWithFlags(&s2, cudaStreamNonBlocking);
        cudaEventCreateWithFlags(&evFork, cudaEventDisableTiming);
        cudaEventCreateWithFlags(&evKV, cudaEventDisableTiming);
        cudaEventCreateWithFlags(&evA, cudaEventDisableTiming);
        cudaEventCreateWithFlags(&evS1, cudaEventDisableTiming);
    }

    // log2(e) folded into the softmax scale; softmax runs in base-2 domain
    const float scale = 0.12753102245150477f;  // (1/sqrt(128)) * log2(e)
    const int gemm_smem = NSTAGE * STAGE_B;
    cudaFuncSetAttribute(gemm_mma_f16, cudaFuncAttributeMaxDynamicSharedMemorySize, gemm_smem);
    const int attn_smem = 128 * AST + 2 * KVST;
    cudaFuncSetAttribute(attn_mma, cudaFuncAttributeMaxDynamicSharedMemorySize, attn_smem);

    // ---- fork ----
    cudaEventRecord(evFork, 0);
    cudaStreamWaitEvent(s1, evFork, 0);
    cudaStreamWaitEvent(s2, evFork, 0);

    // s2: KV chain + Wo prep
    SmallJobs jobs;
    jobs.A[0] = ctx_txt; jobs.W[0] = Wk;  jobs.b[0] = bk;  jobs.C[0] = Kp;  jobs.M[0] = TXT;
    jobs.A[1] = ctx_txt; jobs.W[1] = Wv;  jobs.b[1] = bv;  jobs.C[1] = Vp;  jobs.M[1] = TXT;
    jobs.A[2] = ctx_img; jobs.W[2] = Wak; jobs.b[2] = bak; jobs.C[2] = Kip; jobs.M[2] = IMG;
    jobs.A[3] = ctx_img; jobs.W[3] = Wav; jobs.b[3] = bav; jobs.C[3] = Vip; jobs.M[3] = IMG;
    sgemm_small<<<dim3(DIM / 64, 4, 4), 256, 0, s2>>>(jobs);
    rmsnorm_single<<<TXT, 256, 0, s2>>>(Kp, gk, 1.f, Kh, TXT);
    rmsnorm_single<<<IMGP, 256, 0, s2>>>(Kip, gak, 1.f, Kih, IMG);
    tohalf_pad<<<TXT, 256, 0, s2>>>(Vp, Vh, TXT);
    tohalf_pad<<<IMGP, 256, 0, s2>>>(Vip, Vih, IMG);
    wT_kernel<<<dim3(DIM / 32, DIM / 32), dim3(32, 8), 0, s2>>>(Wo, WoT);
    cudaEventRecord(evKV, s2);

    // main: input conversions + Q projection half 0
    long n4 = (long)NQ * DIM / 4;
    tohalf_flat<<<(unsigned)((n4 + 255) / 256), 256>>>(x, xh, n4);
    wT_kernel<<<dim3(DIM / 32, DIM / 32), dim3(32, 8)>>>(Wq, WqT);
    gemm_mma_f16<<<dim3(DIM / 128, HALF / 128), 256, gemm_smem>>>(xh, WqT, bq, Qp);
    cudaEventRecord(evA, 0);

    // s1: half-0 tail — rmsnorm(h0) -> attn(h0) -> outproj(h0)
    cudaStreamWaitEvent(s1, evA, 0);
    rmsnorm_single<<<HALF, 256, 0, s1>>>(Qp, gq, scale, Qh, HALF);
    cudaStreamWaitEvent(s1, evKV, 0);
    attn_mma<<<dim3(HALF / 128, HEADS), 256, attn_smem, s1>>>(0);
    gemm_mma_f16<<<dim3(DIM / 128, HALF / 128), 256, gemm_smem, s1>>>(Oh, WoT, bo, out);
    cudaEventRecord(evS1, s1);

    // main: half-1 chain
    gemm_mma_f16<<<dim3(DIM / 128, HALF / 128), 256, gemm_smem>>>(
        xh + (long)HALF * DIM, WqT, bq, Qp + (long)HALF * DIM);
    rmsnorm_single<<<HALF, 256>>>(Qp + (long)HALF * DIM, gq, scale, Qh + (long)HALF * DIM, HALF);
    cudaStreamWaitEvent(0, evKV, 0);
    attn_mma<<<dim3(HALF / 128, HEADS), 256, attn_smem>>>(HALF / 128);
    gemm_mma_f16<<<dim3(DIM / 128, HALF / 128), 256, gemm_smem>>>(
        Oh + (long)HALF * DIM, WoT, bo, out + (long)HALF * DIM);

    // join
    cudaStreamWaitEvent(0, evS1, 0);
}

// round 14
// speedup vs baseline: 1.0308x; 1.0308x over previous
#include <cuda_runtime.h>
#include <cuda_fp16.h>
#include <cstdint>

#define DIM 1536
#define HEADS 12
#define HD 128
#define NQ 16384
#define HALF (NQ / 2)
#define IMG 257
#define TXT 512
#define IMGP 320   // img rows padded to multiple of 64

typedef __half h16;

// ---------------- scratch (no allocations allowed) ----------------
__device__ float g_Q[(long)NQ * DIM];
__device__ float g_O[(long)NQ * DIM];          // attention partial (txt segment)
__device__ float g_K[(long)TXT * DIM];
__device__ float g_V[(long)TXT * DIM];
__device__ float g_Ki[(long)IMG * DIM];
__device__ float g_Vi[(long)IMG * DIM];
__device__ h16 g_xh[(long)NQ * DIM];
__device__ h16 g_Qh[(long)NQ * DIM];
__device__ h16 g_Oh[(long)NQ * DIM];
__device__ h16 g_Kh[(long)TXT * DIM];
__device__ h16 g_Vh[(long)TXT * DIM];
__device__ h16 g_Kih[(long)IMGP * DIM];
__device__ h16 g_Vih[(long)IMGP * DIM];
__device__ h16 g_WqT[(long)DIM * DIM];
__device__ h16 g_WoT[(long)DIM * DIM];

// ---------------- PTX helpers ----------------
__device__ __forceinline__ uint32_t s2u(const void* p) {
    return (uint32_t)__cvta_generic_to_shared(p);
}
__device__ __forceinline__ void cp16(uint32_t s, const void* g) {
    asm volatile("cp.async.cg.shared.global [%0], [%1], 16;\n" :: "r"(s), "l"(g) : "memory");
}
__device__ __forceinline__ void cp_commit() {
    asm volatile("cp.async.commit_group;\n" ::: "memory");
}
template <int N>
__device__ __forceinline__ void cp_wait() {
    asm volatile("cp.async.wait_group %0;\n" :: "n"(N) : "memory");
}
__device__ __forceinline__ void ldsm4(uint32_t* r, uint32_t a) {
    asm volatile("ldmatrix.sync.aligned.m8n8.x4.shared.b16 {%0,%1,%2,%3}, [%4];"
                 : "=r"(r[0]), "=r"(r[1]), "=r"(r[2]), "=r"(r[3]) : "r"(a));
}
__device__ __forceinline__ void ldsm4t(uint32_t* r, uint32_t a) {
    asm volatile("ldmatrix.sync.aligned.m8n8.x4.trans.shared.b16 {%0,%1,%2,%3}, [%4];"
                 : "=r"(r[0]), "=r"(r[1]), "=r"(r[2]), "=r"(r[3]) : "r"(a));
}
__device__ __forceinline__ void mma16816(float* c, const uint32_t* a, const uint32_t* b) {
    asm volatile(
        "mma.sync.aligned.m16n8k16.row.col.f32.f16.f16.f32 "
        "{%0,%1,%2,%3}, {%4,%5,%6,%7}, {%8,%9}, {%0,%1,%2,%3};"
        : "+f"(c[0]), "+f"(c[1]), "+f"(c[2]), "+f"(c[3])
        : "r"(a[0]), "r"(a[1]), "r"(a[2]), "r"(a[3]), "r"(b[0]), "r"(b[1]));
}
__device__ __forceinline__ uint32_t packh(float a, float b) {
    __half2 t = __floats2half2_rn(a, b);
    return *(uint32_t*)&t;
}
__device__ __forceinline__ float ex2(float x) {
    float y;
    asm("ex2.approx.ftz.f32 %0, %1;" : "=f"(y) : "f"(x));
    return y;
}

// ---------------- single-pass fp16 HMMA GEMM: C = A @ BT^T + bias ----------------
#define GSTRIDE 80
#define TILE_B (128 * GSTRIDE)
#define STAGE_B (2 * TILE_B)   // A, B
#define NSTAGE 5

__global__ __launch_bounds__(256, 2)
void gemm_mma_f16(const h16* __restrict__ A, const h16* __restrict__ BT,
                  const float* __restrict__ bias, float* __restrict__ C) {
    extern __shared__ char dynsm[];
    const uint32_t smem0 = s2u(dynsm);
    const int tid = threadIdx.x;
    const int lane = tid & 31;
    const int wid = tid >> 5;
    const int wm = wid & 3;
    const int wn = wid >> 2;
    const int m0 = blockIdx.y * 128;
    const int n0 = blockIdx.x * 128;

    const h16* srcs[2] = {A, BT};
    const int bases[2] = {m0, n0};

    auto load_stage = [&](int slot, int k0) {
        const uint32_t sb = smem0 + slot * STAGE_B;
#pragma unroll
        for (int t = 0; t < 4; ++t) {
            const int ch = tid + t * 256;      // 1024 chunks
            const int tile = ch >> 9;
            const int idx = ch & 511;
            const int row = idx >> 2;
            const int cb = idx & 3;
            const uint32_t so = sb + tile * TILE_B + row * GSTRIDE + cb * 16;
            const h16* g = srcs[tile] + (size_t)(bases[tile] + row) * DIM + k0 + cb * 8;
            cp16(so, g);
        }
        cp_commit();
    };

    for (int s = 0; s < NSTAGE; ++s) load_stage(s, s * 32);

    float acc[2][8][4];
#pragma unroll
    for (int mi = 0; mi < 2; ++mi)
#pragma unroll
        for (int nj = 0; nj < 8; ++nj)
#pragma unroll
            for (int r = 0; r < 4; ++r) acc[mi][nj][r] = 0.f;

    const int rowA = wm * 32 + (lane & 15);
    const int acol = (lane >> 4) * 16;
    const int rowB = wn * 64 + (lane >> 4) * 8 + (lane & 7);
    const int bcol = ((lane >> 3) & 1) * 16;

    constexpr int NKC = DIM / 32;
    for (int i = 0; i < NKC; ++i) {
        const int slot = i % NSTAGE;
        const uint32_t sb = smem0 + slot * STAGE_B;
        cp_wait<NSTAGE - 1>();
        __syncthreads();

        const uint32_t aA = sb + rowA * GSTRIDE + acol;
        const uint32_t aB = sb + TILE_B + rowB * GSTRIDE + bcol;

#pragma unroll
        for (int k16 = 0; k16 < 2; ++k16) {
            const uint32_t ko = k16 * 32;
            uint32_t ah[2][4], bh[4][4];
#pragma unroll
            for (int mi = 0; mi < 2; ++mi)
                ldsm4(ah[mi], aA + mi * 16 * GSTRIDE + ko);
#pragma unroll
            for (int ni = 0; ni < 4; ++ni)
                ldsm4(bh[ni], aB + ni * 16 * GSTRIDE + ko);
#pragma unroll
            for (int mi = 0; mi < 2; ++mi)
#pragma unroll
                for (int nj = 0; nj < 8; ++nj)
                    mma16816(acc[mi][nj], ah[mi], &bh[nj >> 1][(nj & 1) * 2]);
        }
        __syncthreads();
        if (i + NSTAGE < NKC) load_stage(slot, (i + NSTAGE) * 32);
        else cp_commit();
    }

    const int crow0 = m0 + wm * 32 + (lane >> 2);
    const int ccol0 = n0 + wn * 64 + (lane & 3) * 2;
#pragma unroll
    for (int nj = 0; nj < 8; ++nj) {
        const int col = ccol0 + nj * 8;
        const float b0 = bias[col], b1 = bias[col + 1];
#pragma unroll
        for (int mi = 0; mi < 2; ++mi) {
            float* c0 = C + (size_t)(crow0 + mi * 16) * DIM + col;
            float* c1 = c0 + 8 * DIM;
            *(float2*)c0 = make_float2(acc[mi][nj][0] + b0, acc[mi][nj][1] + b1);
            *(float2*)c1 = make_float2(acc[mi][nj][2] + b0, acc[mi][nj][3] + b1);
        }
    }
}

// ---------------- flat fp32 -> fp16 convert ----------------
__global__ __launch_bounds__(256)
void tohalf_flat(const float* __restrict__ X, h16* __restrict__ H, long n4) {
    long i = ((long)blockIdx.x * 256 + threadIdx.x);
    if (i >= n4) return;
    float4 v = *((const float4*)X + i);
    __half2* Hp = (__half2*)H + i * 2;
    Hp[0] = __floats2half2_rn(v.x, v.y);
    Hp[1] = __floats2half2_rn(v.z, v.w);
}

// ---------------- transpose weights to single fp16 ----------------
__global__ __launch_bounds__(256)
void wT_kernel(const float* __restrict__ W, h16* __restrict__ Ht) {
    __shared__ float t[32][33];
    const int k0 = blockIdx.y * 32, n0 = blockIdx.x * 32;
    const int tx = threadIdx.x, ty = threadIdx.y;
#pragma unroll
    for (int j = 0; j < 4; ++j)
        t[ty + j * 8][tx] = W[(size_t)(k0 + ty + j * 8) * DIM + n0 + tx];
    __syncthreads();
#pragma unroll
    for (int j = 0; j < 4; ++j)
        Ht[(size_t)(n0 + ty + j * 8) * DIM + k0 + tx] = __float2half(t[tx][ty + j * 8]);
}

// ---------------- small fused SGEMM ----------------
struct SmallJobs {
    const float* A[4];
    const float* W[4];
    const float* b[4];
    float* C[4];
    int M[4];
};

__global__ __launch_bounds__(256)
void sgemm_small(SmallJobs jobs) {
    const int z = blockIdx.z;
    const float* A = jobs.A[z];
    const float* B = jobs.W[z];
    const float* bias = jobs.b[z];
    float* C = jobs.C[z];
    const int M = jobs.M[z];
    const int N = DIM, K = DIM;

    const int m0 = blockIdx.y * 128;
    if (m0 >= M) return;
    const int n0 = blockIdx.x * 64;

    __shared__ float As[16 * 132];
    __shared__ float Bs[16 * 64];
    const int tid = threadIdx.x;
    const int tx = tid & 15;
    const int ty = tid >> 4;
    const int arow = tid >> 1;
    const int ak = (tid & 1) * 8;
    const int brow = tid >> 4;
    const int bcol = (tid & 15) * 4;

    float acc[8][4];
#pragma unroll
    for (int i = 0; i < 8; ++i)
#pragma unroll
        for (int j = 0; j < 4; ++j) acc[i][j] = 0.f;

    const bool avalid = (m0 + arow) < M;
    const float* Aptr = A + (long)(m0 + arow) * K + ak;
    const float* Bptr = B + (long)brow * N + n0 + bcol;

    for (int k0 = 0; k0 < K; k0 += 16) {
        float4 a0 = make_float4(0.f, 0.f, 0.f, 0.f);
        float4 a1 = make_float4(0.f, 0.f, 0.f, 0.f);
        if (avalid) {
            a0 = *(const float4*)(Aptr + k0);
            a1 = *(const float4*)(Aptr + k0 + 4);
        }
        As[(ak + 0) * 132 + arow] = a0.x;
        As[(ak + 1) * 132 + arow] = a0.y;
        As[(ak + 2) * 132 + arow] = a0.z;
        As[(ak + 3) * 132 + arow] = a0.w;
        As[(ak + 4) * 132 + arow] = a1.x;
        As[(ak + 5) * 132 + arow] = a1.y;
        As[(ak + 6) * 132 + arow] = a1.z;
        As[(ak + 7) * 132 + arow] = a1.w;
        *(float4*)(Bs + brow * 64 + bcol) = *(const float4*)(Bptr + (long)k0 * N);
        __syncthreads();
#pragma unroll
        for (int kk = 0; kk < 16; ++kk) {
            float4 x0 = *(const float4*)(As + kk * 132 + ty * 8);
            float4 x1 = *(const float4*)(As + kk * 132 + ty * 8 + 4);
            float4 y = *(const float4*)(Bs + kk * 64 + tx * 4);
            float a[8] = {x0.x, x0.y, x0.z, x0.w, x1.x, x1.y, x1.z, x1.w};
            float b[4] = {y.x, y.y, y.z, y.w};
#pragma unroll
            for (int i = 0; i < 8; ++i)
#pragma unroll
                for (int j = 0; j < 4; ++j) acc[i][j] += a[i] * b[j];
        }
        __syncthreads();
    }

    float4 bv = *(const float4*)(bias + n0 + tx * 4);
    float bb[4] = {bv.x, bv.y, bv.z, bv.w};
#pragma unroll
    for (int i = 0; i < 8; ++i) {
        int m = m0 + ty * 8 + i;
        if (m < M) {
            float4 out;
            out.x = acc[i][0] + bb[0];
            out.y = acc[i][1] + bb[1];
            out.z = acc[i][2] + bb[2];
            out.w = acc[i][3] + bb[3];
            *(float4*)(C + (long)m * N + n0 + tx * 4) = out;
        }
    }
}

// ---------------- RMSNorm -> single fp16 (optional scale), zero-pad ----------------
__global__ __launch_bounds__(256)
void rmsnorm_single(const float* __restrict__ X, const float* __restrict__ g, float scale,
                    h16* __restrict__ H, int nvalid) {
    const int r = blockIdx.x;
    const int tid = threadIdx.x;
    if (r >= nvalid) {
#pragma unroll
        for (int i = 0; i < 6; ++i)
            H[(long)r * DIM + tid + i * 256] = __float2half(0.f);
        return;
    }
    const float* x = X + (long)r * DIM;
    float v[6];
    float ss = 0.f;
#pragma unroll
    for (int i = 0; i < 6; ++i) {
        v[i] = x[tid + i * 256];
        ss += v[i] * v[i];
    }
#pragma unroll
    for (int off = 16; off >= 1; off >>= 1)
        ss += __shfl_xor_sync(0xffffffffu, ss, off);
    __shared__ float red[8];
    if ((tid & 31) == 0) red[tid >> 5] = ss;
    __syncthreads();
    float tot = 0.f;
#pragma unroll
    for (int i = 0; i < 8; ++i) tot += red[i];
    const float rms = rsqrtf(tot * (1.f / (float)DIM) + 1e-6f);
#pragma unroll
    for (int i = 0; i < 6; ++i)
        H[(long)r * DIM + tid + i * 256] = __float2half(v[i] * rms * g[tid + i * 256] * scale);
}

// ---------------- fp16 (single) row convert with zero-pad ----------------
__global__ __launch_bounds__(256)
void tohalf_pad(const float* __restrict__ X, h16* __restrict__ H, int nvalid) {
    const int r = blockIdx.x;
    const int tid = threadIdx.x;
#pragma unroll
    for (int i = 0; i < 6; ++i) {
        float val = (r < nvalid) ? X[(long)r * DIM + tid + i * 256] : 0.f;
        H[(long)r * DIM + tid + i * 256] = __float2half(val);
    }
}

// ---------------- HMMA flash attention ----------------
// Single-pass fp16 QK and PV; exp2-domain softmax; KV double-buffered; 2 CTAs/SM.
#define AST 272            // smem row stride bytes (128 fp16 + 16B pad)
#define KVROW (64 * AST)
#define KVST (2 * KVROW)   // Kh, Vh per stage

__global__ __launch_bounds__(256, 2)
void attn_mma(int qb0) {
    extern __shared__ char smem[];
    const uint32_t sQh = s2u(smem);
    const uint32_t sKV = sQh + 128 * AST;   // 2 stages of KVST

    const int tid = threadIdx.x, lane = tid & 31, wid = tid >> 5;
    const int qb = blockIdx.x + qb0, h = blockIdx.y;
    const long qrow0 = (long)qb * 128;

    // Q load (its own commit group)
    {
        const h16* Qhg = g_Qh + qrow0 * DIM + h * HD;
#pragma unroll
        for (int t = 0; t < 8; ++t) {
            int c = tid + t * 256;
            int r = c >> 4, cb = c & 15;
            cp16(sQh + r * AST + cb * 16, Qhg + (long)r * DIM + cb * 8);
        }
        cp_commit();
    }

    const uint32_t qoff = (uint32_t)((wid * 16 + (lane & 15)) * AST + (lane >> 4) * 16);
    const uint32_t koff = (uint32_t)((((lane >> 4) << 3) + (lane & 7)) * AST + ((lane >> 3) & 1) * 16);
    const uint32_t voff = (uint32_t)(((((lane >> 3) & 1) << 3) + (lane & 7)) * AST + (lane >> 4) * 16);

    const int r0 = lane >> 2;
    const int colb = (lane & 3) * 2;

#pragma unroll 1
    for (int seg = 0; seg < 2; ++seg) {
        const h16 *Khg, *Vhg;
        int len, ntiles;
        if (seg == 0) {
            Khg = g_Kh; Vhg = g_Vh;
            len = TXT; ntiles = TXT / 64;
        } else {
            Khg = g_Kih; Vhg = g_Vih;
            len = IMG; ntiles = IMGP / 64;
        }

        auto load_kv = [&](int stage, int t) {
            const uint32_t sb = sKV + stage * KVST;
            const long kvbase = (long)t * 64 * DIM + h * HD;
            const h16* arrs[2] = {Khg, Vhg};
#pragma unroll
            for (int tt = 0; tt < 8; ++tt) {
                int c = tid + tt * 256;       // 2048 chunks
                int arr = c >> 10;
                int idx = c & 1023;
                int r = idx >> 4, cb = idx & 15;
                cp16(sb + arr * KVROW + r * AST + cb * 16,
                     arrs[arr] + kvbase + (long)r * DIM + cb * 8);
            }
            cp_commit();
        };

        load_kv(0, 0);  // prologue

        float mrow0 = -1e30f, mrow1 = -1e30f, lsum0 = 0.f, lsum1 = 0.f;
        float O[16][4];
#pragma unroll
        for (int j = 0; j < 16; ++j)
#pragma unroll
            for (int e = 0; e < 4; ++e) O[j][e] = 0.f;

#pragma unroll 1
        for (int t = 0; t < ntiles; ++t) {
            __syncthreads();   // all warps finished reading buffer (t+1)&1 (from iter t-1)
            if (t + 1 < ntiles) {
                load_kv((t + 1) & 1, t + 1);
                cp_wait<1>();
            } else {
                cp_wait<0>();
            }
            __syncthreads();   // buffer t&1 visible to all

            const uint32_t sb = sKV + (t & 1) * KVST;
            const uint32_t sKh_ = sb, sVh_ = sb + KVROW;

            // ---- S = Q K^T (single fp16 pass, log2-domain logits) ----
            float S[8][4];
#pragma unroll
            for (int j = 0; j < 8; ++j)
#pragma unroll
                for (int e = 0; e < 4; ++e) S[j][e] = 0.f;
#pragma unroll
            for (int k16 = 0; k16 < 8; ++k16) {
                uint32_t ah[4];
                ldsm4(ah, sQh + qoff + k16 * 32);
#pragma unroll
                for (int nt2 = 0; nt2 < 4; ++nt2) {
                    uint32_t bh[4];
                    ldsm4(bh, sKh_ + koff + nt2 * 16 * AST + k16 * 32);
                    mma16816(S[2 * nt2], ah, bh);
                    mma16816(S[2 * nt2 + 1], ah, bh + 2);
                }
            }

            // ---- online softmax (base-2) ----
            const int t0 = t * 64;
            if (t0 + 64 > len) {
#pragma unroll
                for (int j = 0; j < 8; ++j) {
#pragma unroll
                    for (int e = 0; e < 2; ++e) {
                        if (t0 + j * 8 + colb + e >= len) {
                            S[j][e] = -1e30f;
                            S[j][2 + e] = -1e30f;
                        }
                    }
                }
            }
            float mx0 = -1e30f, mx1 = -1e30f;
#pragma unroll
            for (int j = 0; j < 8; ++j) {
                mx0 = fmaxf(mx0, fmaxf(S[j][0], S[j][1]));
                mx1 = fmaxf(mx1, fmaxf(S[j][2], S[j][3]));
            }
            mx0 = fmaxf(mx0, __shfl_xor_sync(0xffffffffu, mx0, 1));
            mx0 = fmaxf(mx0, __shfl_xor_sync(0xffffffffu, mx0, 2));
            mx1 = fmaxf(mx1, __shfl_xor_sync(0xffffffffu, mx1, 1));
            mx1 = fmaxf(mx1, __shfl_xor_sync(0xffffffffu, mx1, 2));
            const float nm0 = fmaxf(mrow0, mx0);
            const float nm1 = fmaxf(mrow1, mx1);
            const float sc0 = ex2(mrow0 - nm0);
            const float sc1 = ex2(mrow1 - nm1);
            mrow0 = nm0; mrow1 = nm1;

            uint32_t Ph[8][2];
            float rs0 = 0.f, rs1 = 0.f;
#pragma unroll
            for (int j = 0; j < 8; ++j) {
                float p0 = ex2(S[j][0] - nm0);
                float p1 = ex2(S[j][1] - nm0);
                float p2 = ex2(S[j][2] - nm1);
                float p3 = ex2(S[j][3] - nm1);
                rs0 += p0 + p1;
                rs1 += p2 + p3;
                Ph[j][0] = packh(p0, p1);
                Ph[j][1] = packh(p2, p3);
            }
            rs0 += __shfl_xor_sync(0xffffffffu, rs0, 1);
            rs0 += __shfl_xor_sync(0xffffffffu, rs0, 2);
            rs1 += __shfl_xor_sync(0xffffffffu, rs1, 1);
            rs1 += __shfl_xor_sync(0xffffffffu, rs1, 2);
            lsum0 = lsum0 * sc0 + rs0;
            lsum1 = lsum1 * sc1 + rs1;
#pragma unroll
            for (int j = 0; j < 16; ++j) {
                O[j][0] *= sc0; O[j][1] *= sc0;
                O[j][2] *= sc1; O[j][3] *= sc1;
            }

            // ---- O += P V (single pass) ----
#pragma unroll
            for (int s = 0; s < 4; ++s) {
                uint32_t pah[4] = {Ph[2 * s][0], Ph[2 * s][1], Ph[2 * s + 1][0], Ph[2 * s + 1][1]};
#pragma unroll
                for (int d2 = 0; d2 < 8; ++d2) {
                    uint32_t vh[4];
                    ldsm4t(vh, sVh_ + voff + s * 16 * AST + d2 * 32);
                    mma16816(O[2 * d2], pah, vh);
                    mma16816(O[2 * d2 + 1], pah, vh + 2);
                }
            }
        }

        const float inv0 = 1.f / lsum0;
        const float inv1 = 1.f / lsum1;
        const long grow0 = qrow0 + wid * 16 + r0;
        const long grow1 = grow0 + 8;
        if (seg == 0) {
#pragma unroll
            for (int j = 0; j < 16; ++j) {
                const int d = h * HD + j * 8 + colb;
                *(float2*)(g_O + grow0 * DIM + d) = make_float2(O[j][0] * inv0, O[j][1] * inv0);
                *(float2*)(g_O + grow1 * DIM + d) = make_float2(O[j][2] * inv1, O[j][3] * inv1);
            }
        } else {
#pragma unroll
            for (int j = 0; j < 16; ++j) {
                const int d = h * HD + j * 8 + colb;
                float2 p0 = *(float2*)(g_O + grow0 * DIM + d);
                float2 p1 = *(float2*)(g_O + grow1 * DIM + d);
                *(__half2*)(g_Oh + grow0 * DIM + d) =
                    __floats2half2_rn(p0.x + O[j][0] * inv0, p0.y + O[j][1] * inv0);
                *(__half2*)(g_Oh + grow1 * DIM + d) =
                    __floats2half2_rn(p1.x + O[j][2] * inv1, p1.y + O[j][3] * inv1);
            }
        }
    }
}

// ---------------- launch ----------------
extern "C" void kernel_launch(void* const* d_in, const int* in_sizes, int n_in,
                              void* d_out, int out_size) {
    const float* x       = (const float*)d_in[0];
    const float* context = (const float*)d_in[1];
    const float* Wq  = (const float*)d_in[3];
    const float* bq  = (const float*)d_in[4];
    const float* Wk  = (const float*)d_in[5];
    const float* bk  = (const float*)d_in[6];
    const float* Wv  = (const float*)d_in[7];
    const float* bv  = (const float*)d_in[8];
    const float* Wak = (const float*)d_in[9];
    const float* bak = (const float*)d_in[10];
    const float* Wav = (const float*)d_in[11];
    const float* bav = (const float*)d_in[12];
    const float* Wo  = (const float*)d_in[13];
    const float* bo  = (const float*)d_in[14];
    const float* gq  = (const float*)d_in[15];
    const float* gk  = (const float*)d_in[16];
    const float* gak = (const float*)d_in[17];
    float* out = (float*)d_out;

    float *Qp, *Kp, *Vp, *Kip, *Vip;
    h16 *xh, *Oh, *WqT, *WoT;
    h16 *Qh, *Kh, *Vh, *Kih, *Vih;
    cudaGetSymbolAddress((void**)&Qp, g_Q);
    cudaGetSymbolAddress((void**)&Kp, g_K);
    cudaGetSymbolAddress((void**)&Vp, g_V);
    cudaGetSymbolAddress((void**)&Kip, g_Ki);
    cudaGetSymbolAddress((void**)&Vip, g_Vi);
    cudaGetSymbolAddress((void**)&xh, g_xh);
    cudaGetSymbolAddress((void**)&Oh, g_Oh);
    cudaGetSymbolAddress((void**)&WqT, g_WqT);
    cudaGetSymbolAddress((void**)&WoT, g_WoT);
    cudaGetSymbolAddress((void**)&Qh, g_Qh);
    cudaGetSymbolAddress((void**)&Kh, g_Kh);
    cudaGetSymbolAddress((void**)&Vh, g_Vh);
    cudaGetSymbolAddress((void**)&Kih, g_Kih);
    cudaGetSymbolAddress((void**)&Vih, g_Vih);

    const float* ctx_img = context;
    const float* ctx_txt = context + (long)IMG * DIM;

    static cudaStream_t s1 = nullptr, s2 = nullptr;
    static cudaEvent_t evFork = nullptr, evKV = nullptr, evA = nullptr, evS1 = nullptr;
    if (s1 == nullptr) {
        cudaStreamCreateWithFlags(&s1, cudaStreamNonBlocking);
        cudaStreamCreateWithFlags(&s2, cudaStreamNonBlocking);
        cudaEventCreateWithFlags(&evFork, cudaEventDisableTiming);
        cudaEventCreateWithFlags(&evKV, cudaEventDisableTiming);
        cudaEventCreateWithFlags(&evA, cudaEventDisableTiming);
        cudaEventCreateWithFlags(&evS1, cudaEventDisableTiming);
    }

    // log2(e) folded into the softmax scale; softmax runs in base-2 domain
    const float scale = 0.12753102245150477f;  // (1/sqrt(128)) * log2(e)
    const int gemm_smem = NSTAGE * STAGE_B;
    cudaFuncSetAttribute(gemm_mma_f16, cudaFuncAttributeMaxDynamicSharedMemorySize, gemm_smem);
    const int attn_smem = 128 * AST + 2 * KVST;
    cudaFuncSetAttribute(attn_mma, cudaFuncAttributeMaxDynamicSharedMemorySize, attn_smem);

    // ---- fork ----
    cudaEventRecord(evFork, 0);
    cudaStreamWaitEvent(s1, evFork, 0);
    cudaStreamWaitEvent(s2, evFork, 0);

    // s2: KV chain + Wo prep
    SmallJobs jobs;
    jobs.A[0] = ctx_txt; jobs.W[0] = Wk;  jobs.b[0] = bk;  jobs.C[0] = Kp;  jobs.M[0] = TXT;
    jobs.A[1] = ctx_txt; jobs.W[1] = Wv;  jobs.b[1] = bv;  jobs.C[1] = Vp;  jobs.M[1] = TXT;
    jobs.A[2] = ctx_img; jobs.W[2] = Wak; jobs.b[2] = bak; jobs.C[2] = Kip; jobs.M[2] = IMG;
    jobs.A[3] = ctx_img; jobs.W[3] = Wav; jobs.b[3] = bav; jobs.C[3] = Vip; jobs.M[3] = IMG;
    sgemm_small<<<dim3(DIM / 64, 4, 4), 256, 0, s2>>>(jobs);
    rmsnorm_single<<<TXT, 256, 0, s2>>>(Kp, gk, 1.f, Kh, TXT);
    rmsnorm_single<<<IMGP, 256, 0, s2>>>(Kip, gak, 1.f, Kih, IMG);
    tohalf_pad<<<TXT, 256, 0, s2>>>(Vp, Vh, TXT);
    tohalf_pad<<<IMGP, 256, 0, s2>>>(Vip, Vih, IMG);
    wT_kernel<<<dim3(DIM / 32, DIM / 32), dim3(32, 8), 0, s2>>>(Wo, WoT);
    cudaEventRecord(evKV, s2);

    // main: input conversions + Q projection half 0
    long n4 = (long)NQ * DIM / 4;
    tohalf_flat<<<(unsigned)((n4 + 255) / 256), 256>>>(x, xh, n4);
    wT_kernel<<<dim3(DIM / 32, DIM / 32), dim3(32, 8)>>>(Wq, WqT);
    gemm_mma_f16<<<dim3(DIM / 128, HALF / 128), 256, gemm_smem>>>(xh, WqT, bq, Qp);
    cudaEventRecord(evA, 0);

    // s1: half-0 tail — rmsnorm(h0) -> attn(h0) -> outproj(h0)
    cudaStreamWaitEvent(s1, evA, 0);
    rmsnorm_single<<<HALF, 256, 0, s1>>>(Qp, gq, scale, Qh, HALF);
    cudaStreamWaitEvent(s1, evKV, 0);
    attn_mma<<<dim3(HALF / 128, HEADS), 256, attn_smem, s1>>>(0);
    gemm_mma_f16<<<dim3(DIM / 128, HALF / 128), 256, gemm_smem, s1>>>(Oh, WoT, bo, out);
    cudaEventRecord(evS1, s1);

    // main: half-1 chain
    gemm_mma_f16<<<dim3(DIM / 128, HALF / 128), 256, gemm_smem>>>(
        xh + (long)HALF * DIM, WqT, bq, Qp + (long)HALF * DIM);
    rmsnorm_single<<<HALF, 256>>>(Qp + (long)HALF * DIM, gq, scale, Qh + (long)HALF * DIM, HALF);
    cudaStreamWaitEvent(0, evKV, 0);
    attn_mma<<<dim3(HALF / 128, HEADS), 256, attn_smem>>>(HALF / 128);
    gemm_mma_f16<<<dim3(DIM / 128, HALF / 128), 256, gemm_smem>>>(
        Oh + (long)HALF * DIM, WoT, bo, out + (long)HALF * DIM);

    // join
    cudaStreamWaitEvent(0, evS1, 0);
}

// round 15
// speedup vs baseline: 1.0404x; 1.0093x over previous
#include <cuda_runtime.h>
#include <cuda_fp16.h>
#include <cstdint>

#define DIM 1536
#define HEADS 12
#define HD 128
#define NQ 16384
#define HALF (NQ / 2)
#define IMG 257
#define TXT 512
#define IMGP 320   // img rows padded for attention tiles
#define IMGG 384   // img rows padded for 128-row GEMM tiles

typedef __half h16;

// ---------------- scratch (no allocations allowed) ----------------
__device__ float g_Q[(long)NQ * DIM];
__device__ float g_K[(long)TXT * DIM];
__device__ float g_V[(long)TXT * DIM];
__device__ float g_Ki[(long)IMGG * DIM];
__device__ float g_Vi[(long)IMGG * DIM];
__device__ h16 g_Op[(long)NQ * DIM];          // attention partial (txt segment), fp16
__device__ h16 g_xh[(long)NQ * DIM];
__device__ h16 g_cth[(long)TXT * DIM];        // ctx_txt fp16
__device__ h16 g_cih[(long)IMGG * DIM];       // ctx_img fp16 (zero-padded)
__device__ h16 g_Qh[(long)NQ * DIM];
__device__ h16 g_Oh[(long)NQ * DIM];
__device__ h16 g_Kh[(long)TXT * DIM];
__device__ h16 g_Vh[(long)TXT * DIM];
__device__ h16 g_Kih[(long)IMGP * DIM];
__device__ h16 g_Vih[(long)IMGP * DIM];
__device__ h16 g_WqT[(long)DIM * DIM];
__device__ h16 g_WkT[(long)DIM * DIM];
__device__ h16 g_WvT[(long)DIM * DIM];
__device__ h16 g_WakT[(long)DIM * DIM];
__device__ h16 g_WavT[(long)DIM * DIM];
__device__ h16 g_WoT[(long)DIM * DIM];

// ---------------- PTX helpers ----------------
__device__ __forceinline__ uint32_t s2u(const void* p) {
    return (uint32_t)__cvta_generic_to_shared(p);
}
__device__ __forceinline__ void cp16(uint32_t s, const void* g) {
    asm volatile("cp.async.cg.shared.global [%0], [%1], 16;\n" :: "r"(s), "l"(g) : "memory");
}
__device__ __forceinline__ void cp_commit() {
    asm volatile("cp.async.commit_group;\n" ::: "memory");
}
template <int N>
__device__ __forceinline__ void cp_wait() {
    asm volatile("cp.async.wait_group %0;\n" :: "n"(N) : "memory");
}
__device__ __forceinline__ void ldsm4(uint32_t* r, uint32_t a) {
    asm volatile("ldmatrix.sync.aligned.m8n8.x4.shared.b16 {%0,%1,%2,%3}, [%4];"
                 : "=r"(r[0]), "=r"(r[1]), "=r"(r[2]), "=r"(r[3]) : "r"(a));
}
__device__ __forceinline__ void ldsm4t(uint32_t* r, uint32_t a) {
    asm volatile("ldmatrix.sync.aligned.m8n8.x4.trans.shared.b16 {%0,%1,%2,%3}, [%4];"
                 : "=r"(r[0]), "=r"(r[1]), "=r"(r[2]), "=r"(r[3]) : "r"(a));
}
__device__ __forceinline__ void mma16816(float* c, const uint32_t* a, const uint32_t* b) {
    asm volatile(
        "mma.sync.aligned.m16n8k16.row.col.f32.f16.f16.f32 "
        "{%0,%1,%2,%3}, {%4,%5,%6,%7}, {%8,%9}, {%0,%1,%2,%3};"
        : "+f"(c[0]), "+f"(c[1]), "+f"(c[2]), "+f"(c[3])
        : "r"(a[0]), "r"(a[1]), "r"(a[2]), "r"(a[3]), "r"(b[0]), "r"(b[1]));
}
__device__ __forceinline__ uint32_t packh(float a, float b) {
    __half2 t = __floats2half2_rn(a, b);
    return *(uint32_t*)&t;
}
__device__ __forceinline__ float ex2(float x) {
    float y;
    asm("ex2.approx.ftz.f32 %0, %1;" : "=f"(y) : "f"(x));
    return y;
}

// ---------------- single-pass fp16 HMMA GEMM: C = A @ BT^T + bias ----------------
#define GSTRIDE 80
#define TILE_B (128 * GSTRIDE)
#define STAGE_B (2 * TILE_B)   // A, B
#define NSTAGE 5

__global__ __launch_bounds__(256, 2)
void gemm_mma_f16(const h16* __restrict__ A, const h16* __restrict__ BT,
                  const float* __restrict__ bias, float* __restrict__ C) {
    extern __shared__ char dynsm[];
    const uint32_t smem0 = s2u(dynsm);
    const int tid = threadIdx.x;
    const int lane = tid & 31;
    const int wid = tid >> 5;
    const int wm = wid & 3;
    const int wn = wid >> 2;
    const int m0 = blockIdx.y * 128;
    const int n0 = blockIdx.x * 128;

    const h16* srcs[2] = {A, BT};
    const int bases[2] = {m0, n0};

    auto load_stage = [&](int slot, int k0) {
        const uint32_t sb = smem0 + slot * STAGE_B;
#pragma unroll
        for (int t = 0; t < 4; ++t) {
            const int ch = tid + t * 256;      // 1024 chunks
            const int tile = ch >> 9;
            const int idx = ch & 511;
            const int row = idx >> 2;
            const int cb = idx & 3;
            const uint32_t so = sb + tile * TILE_B + row * GSTRIDE + cb * 16;
            const h16* g = srcs[tile] + (size_t)(bases[tile] + row) * DIM + k0 + cb * 8;
            cp16(so, g);
        }
        cp_commit();
    };

    for (int s = 0; s < NSTAGE; ++s) load_stage(s, s * 32);

    float acc[2][8][4];
#pragma unroll
    for (int mi = 0; mi < 2; ++mi)
#pragma unroll
        for (int nj = 0; nj < 8; ++nj)
#pragma unroll
            for (int r = 0; r < 4; ++r) acc[mi][nj][r] = 0.f;

    const int rowA = wm * 32 + (lane & 15);
    const int acol = (lane >> 4) * 16;
    const int rowB = wn * 64 + (lane >> 4) * 8 + (lane & 7);
    const int bcol = ((lane >> 3) & 1) * 16;

    constexpr int NKC = DIM / 32;
    for (int i = 0; i < NKC; ++i) {
        const int slot = i % NSTAGE;
        const uint32_t sb = smem0 + slot * STAGE_B;
        cp_wait<NSTAGE - 1>();
        __syncthreads();

        const uint32_t aA = sb + rowA * GSTRIDE + acol;
        const uint32_t aB = sb + TILE_B + rowB * GSTRIDE + bcol;

#pragma unroll
        for (int k16 = 0; k16 < 2; ++k16) {
            const uint32_t ko = k16 * 32;
            uint32_t ah[2][4], bh[4][4];
#pragma unroll
            for (int mi = 0; mi < 2; ++mi)
                ldsm4(ah[mi], aA + mi * 16 * GSTRIDE + ko);
#pragma unroll
            for (int ni = 0; ni < 4; ++ni)
                ldsm4(bh[ni], aB + ni * 16 * GSTRIDE + ko);
#pragma unroll
            for (int mi = 0; mi < 2; ++mi)
#pragma unroll
                for (int nj = 0; nj < 8; ++nj)
                    mma16816(acc[mi][nj], ah[mi], &bh[nj >> 1][(nj & 1) * 2]);
        }
        __syncthreads();
        if (i + NSTAGE < NKC) load_stage(slot, (i + NSTAGE) * 32);
        else cp_commit();
    }

    const int crow0 = m0 + wm * 32 + (lane >> 2);
    const int ccol0 = n0 + wn * 64 + (lane & 3) * 2;
#pragma unroll
    for (int nj = 0; nj < 8; ++nj) {
        const int col = ccol0 + nj * 8;
        const float b0 = bias[col], b1 = bias[col + 1];
#pragma unroll
        for (int mi = 0; mi < 2; ++mi) {
            float* c0 = C + (size_t)(crow0 + mi * 16) * DIM + col;
            float* c1 = c0 + 8 * DIM;
            *(float2*)c0 = make_float2(acc[mi][nj][0] + b0, acc[mi][nj][1] + b1);
            *(float2*)c1 = make_float2(acc[mi][nj][2] + b0, acc[mi][nj][3] + b1);
        }
    }
}

// ---------------- flat fp32 -> fp16 convert ----------------
__global__ __launch_bounds__(256)
void tohalf_flat(const float* __restrict__ X, h16* __restrict__ H, long n4) {
    long i = ((long)blockIdx.x * 256 + threadIdx.x);
    if (i >= n4) return;
    float4 v = *((const float4*)X + i);
    __half2* Hp = (__half2*)H + i * 2;
    Hp[0] = __floats2half2_rn(v.x, v.y);
    Hp[1] = __floats2half2_rn(v.z, v.w);
}

// ---------------- transpose weights to single fp16 (batched) ----------------
struct WTJobs {
    const float* W[5];
    h16* O[5];
};

__global__ __launch_bounds__(256)
void wTb_kernel(WTJobs jobs) {
    const int z = blockIdx.z;
    const float* W = jobs.W[z];
    h16* Ht = jobs.O[z];
    __shared__ float t[32][33];
    const int k0 = blockIdx.y * 32, n0 = blockIdx.x * 32;
    const int tx = threadIdx.x, ty = threadIdx.y;
#pragma unroll
    for (int j = 0; j < 4; ++j)
        t[ty + j * 8][tx] = W[(size_t)(k0 + ty + j * 8) * DIM + n0 + tx];
    __syncthreads();
#pragma unroll
    for (int j = 0; j < 4; ++j)
        Ht[(size_t)(n0 + ty + j * 8) * DIM + k0 + tx] = __float2half(t[tx][ty + j * 8]);
}

__global__ __launch_bounds__(256)
void wT_kernel(const float* __restrict__ W, h16* __restrict__ Ht) {
    __shared__ float t[32][33];
    const int k0 = blockIdx.y * 32, n0 = blockIdx.x * 32;
    const int tx = threadIdx.x, ty = threadIdx.y;
#pragma unroll
    for (int j = 0; j < 4; ++j)
        t[ty + j * 8][tx] = W[(size_t)(k0 + ty + j * 8) * DIM + n0 + tx];
    __syncthreads();
#pragma unroll
    for (int j = 0; j < 4; ++j)
        Ht[(size_t)(n0 + ty + j * 8) * DIM + k0 + tx] = __float2half(t[tx][ty + j * 8]);
}

// ---------------- RMSNorm -> single fp16 (optional scale), zero-pad ----------------
__global__ __launch_bounds__(256)
void rmsnorm_single(const float* __restrict__ X, const float* __restrict__ g, float scale,
                    h16* __restrict__ H, int nvalid) {
    const int r = blockIdx.x;
    const int tid = threadIdx.x;
    if (r >= nvalid) {
#pragma unroll
        for (int i = 0; i < 6; ++i)
            H[(long)r * DIM + tid + i * 256] = __float2half(0.f);
        return;
    }
    const float* x = X + (long)r * DIM;
    float v[6];
    float ss = 0.f;
#pragma unroll
    for (int i = 0; i < 6; ++i) {
        v[i] = x[tid + i * 256];
        ss += v[i] * v[i];
    }
#pragma unroll
    for (int off = 16; off >= 1; off >>= 1)
        ss += __shfl_xor_sync(0xffffffffu, ss, off);
    __shared__ float red[8];
    if ((tid & 31) == 0) red[tid >> 5] = ss;
    __syncthreads();
    float tot = 0.f;
#pragma unroll
    for (int i = 0; i < 8; ++i) tot += red[i];
    const float rms = rsqrtf(tot * (1.f / (float)DIM) + 1e-6f);
#pragma unroll
    for (int i = 0; i < 6; ++i)
        H[(long)r * DIM + tid + i * 256] = __float2half(v[i] * rms * g[tid + i * 256] * scale);
}

// ---------------- fp16 (single) row convert with zero-pad ----------------
__global__ __launch_bounds__(256)
void tohalf_pad(const float* __restrict__ X, h16* __restrict__ H, int nvalid) {
    const int r = blockIdx.x;
    const int tid = threadIdx.x;
#pragma unroll
    for (int i = 0; i < 6; ++i) {
        float val = (r < nvalid) ? X[(long)r * DIM + tid + i * 256] : 0.f;
        H[(long)r * DIM + tid + i * 256] = __float2half(val);
    }
}

// ---------------- HMMA flash attention ----------------
// Single-pass fp16 QK and PV; exp2-domain softmax; KV double-buffered; 2 CTAs/SM.
#define AST 272            // smem row stride bytes (128 fp16 + 16B pad)
#define KVROW (64 * AST)
#define KVST (2 * KVROW)   // Kh, Vh per stage

__global__ __launch_bounds__(256, 2)
void attn_mma(int qb0) {
    extern __shared__ char smem[];
    const uint32_t sQh = s2u(smem);
    const uint32_t sKV = sQh + 128 * AST;   // 2 stages of KVST

    const int tid = threadIdx.x, lane = tid & 31, wid = tid >> 5;
    const int qb = blockIdx.x + qb0, h = blockIdx.y;
    const long qrow0 = (long)qb * 128;

    // Q load (its own commit group)
    {
        const h16* Qhg = g_Qh + qrow0 * DIM + h * HD;
#pragma unroll
        for (int t = 0; t < 8; ++t) {
            int c = tid + t * 256;
            int r = c >> 4, cb = c & 15;
            cp16(sQh + r * AST + cb * 16, Qhg + (long)r * DIM + cb * 8);
        }
        cp_commit();
    }

    const uint32_t qoff = (uint32_t)((wid * 16 + (lane & 15)) * AST + (lane >> 4) * 16);
    const uint32_t koff = (uint32_t)((((lane >> 4) << 3) + (lane & 7)) * AST + ((lane >> 3) & 1) * 16);
    const uint32_t voff = (uint32_t)(((((lane >> 3) & 1) << 3) + (lane & 7)) * AST + (lane >> 4) * 16);

    const int r0 = lane >> 2;
    const int colb = (lane & 3) * 2;

#pragma unroll 1
    for (int seg = 0; seg < 2; ++seg) {
        const h16 *Khg, *Vhg;
        int len, ntiles;
        if (seg == 0) {
            Khg = g_Kh; Vhg = g_Vh;
            len = TXT; ntiles = TXT / 64;
        } else {
            Khg = g_Kih; Vhg = g_Vih;
            len = IMG; ntiles = IMGP / 64;
        }

        auto load_kv = [&](int stage, int t) {
            const uint32_t sb = sKV + stage * KVST;
            const long kvbase = (long)t * 64 * DIM + h * HD;
            const h16* arrs[2] = {Khg, Vhg};
#pragma unroll
            for (int tt = 0; tt < 8; ++tt) {
                int c = tid + tt * 256;       // 2048 chunks
                int arr = c >> 10;
                int idx = c & 1023;
                int r = idx >> 4, cb = idx & 15;
                cp16(sb + arr * KVROW + r * AST + cb * 16,
                     arrs[arr] + kvbase + (long)r * DIM + cb * 8);
            }
            cp_commit();
        };

        load_kv(0, 0);  // prologue

        float mrow0 = -1e30f, mrow1 = -1e30f, lsum0 = 0.f, lsum1 = 0.f;
        float O[16][4];
#pragma unroll
        for (int j = 0; j < 16; ++j)
#pragma unroll
            for (int e = 0; e < 4; ++e) O[j][e] = 0.f;

#pragma unroll 1
        for (int t = 0; t < ntiles; ++t) {
            __syncthreads();   // all warps finished reading buffer (t+1)&1 (from iter t-1)
            if (t + 1 < ntiles) {
                load_kv((t + 1) & 1, t + 1);
                cp_wait<1>();
            } else {
                cp_wait<0>();
            }
            __syncthreads();   // buffer t&1 visible to all

            const uint32_t sb = sKV + (t & 1) * KVST;
            const uint32_t sKh_ = sb, sVh_ = sb + KVROW;

            // ---- S = Q K^T (single fp16 pass, log2-domain logits) ----
            float S[8][4];
#pragma unroll
            for (int j = 0; j < 8; ++j)
#pragma unroll
                for (int e = 0; e < 4; ++e) S[j][e] = 0.f;
#pragma unroll
            for (int k16 = 0; k16 < 8; ++k16) {
                uint32_t ah[4];
                ldsm4(ah, sQh + qoff + k16 * 32);
#pragma unroll
                for (int nt2 = 0; nt2 < 4; ++nt2) {
                    uint32_t bh[4];
                    ldsm4(bh, sKh_ + koff + nt2 * 16 * AST + k16 * 32);
                    mma16816(S[2 * nt2], ah, bh);
                    mma16816(S[2 * nt2 + 1], ah, bh + 2);
                }
            }

            // ---- online softmax (base-2) ----
            const int t0 = t * 64;
            if (t0 + 64 > len) {
#pragma unroll
                for (int j = 0; j < 8; ++j) {
#pragma unroll
                    for (int e = 0; e < 2; ++e) {
                        if (t0 + j * 8 + colb + e >= len) {
                            S[j][e] = -1e30f;
                            S[j][2 + e] = -1e30f;
                        }
                    }
                }
            }
            float mx0 = -1e30f, mx1 = -1e30f;
#pragma unroll
            for (int j = 0; j < 8; ++j) {
                mx0 = fmaxf(mx0, fmaxf(S[j][0], S[j][1]));
                mx1 = fmaxf(mx1, fmaxf(S[j][2], S[j][3]));
            }
            mx0 = fmaxf(mx0, __shfl_xor_sync(0xffffffffu, mx0, 1));
            mx0 = fmaxf(mx0, __shfl_xor_sync(0xffffffffu, mx0, 2));
            mx1 = fmaxf(mx1, __shfl_xor_sync(0xffffffffu, mx1, 1));
            mx1 = fmaxf(mx1, __shfl_xor_sync(0xffffffffu, mx1, 2));
            const float nm0 = fmaxf(mrow0, mx0);
            const float nm1 = fmaxf(mrow1, mx1);
            const float sc0 = ex2(mrow0 - nm0);
            const float sc1 = ex2(mrow1 - nm1);
            mrow0 = nm0; mrow1 = nm1;

            uint32_t Ph[8][2];
            float rs0 = 0.f, rs1 = 0.f;
#pragma unroll
            for (int j = 0; j < 8; ++j) {
                float p0 = ex2(S[j][0] - nm0);
                float p1 = ex2(S[j][1] - nm0);
                float p2 = ex2(S[j][2] - nm1);
                float p3 = ex2(S[j][3] - nm1);
                rs0 += p0 + p1;
                rs1 += p2 + p3;
                Ph[j][0] = packh(p0, p1);
                Ph[j][1] = packh(p2, p3);
            }
            rs0 += __shfl_xor_sync(0xffffffffu, rs0, 1);
            rs0 += __shfl_xor_sync(0xffffffffu, rs0, 2);
            rs1 += __shfl_xor_sync(0xffffffffu, rs1, 1);
            rs1 += __shfl_xor_sync(0xffffffffu, rs1, 2);
            lsum0 = lsum0 * sc0 + rs0;
            lsum1 = lsum1 * sc1 + rs1;
#pragma unroll
            for (int j = 0; j < 16; ++j) {
                O[j][0] *= sc0; O[j][1] *= sc0;
                O[j][2] *= sc1; O[j][3] *= sc1;
            }

            // ---- O += P V (single pass) ----
#pragma unroll
            for (int s = 0; s < 4; ++s) {
                uint32_t pah[4] = {Ph[2 * s][0], Ph[2 * s][1], Ph[2 * s + 1][0], Ph[2 * s + 1][1]};
#pragma unroll
                for (int d2 = 0; d2 < 8; ++d2) {
                    uint32_t vh[4];
                    ldsm4t(vh, sVh_ + voff + s * 16 * AST + d2 * 32);
                    mma16816(O[2 * d2], pah, vh);
                    mma16816(O[2 * d2 + 1], pah, vh + 2);
                }
            }
        }

        const float inv0 = 1.f / lsum0;
        const float inv1 = 1.f / lsum1;
        const long grow0 = qrow0 + wid * 16 + r0;
        const long grow1 = grow0 + 8;
        if (seg == 0) {
#pragma unroll
            for (int j = 0; j < 16; ++j) {
                const int d = h * HD + j * 8 + colb;
                *(__half2*)(g_Op + grow0 * DIM + d) =
                    __floats2half2_rn(O[j][0] * inv0, O[j][1] * inv0);
                *(__half2*)(g_Op + grow1 * DIM + d) =
                    __floats2half2_rn(O[j][2] * inv1, O[j][3] * inv1);
            }
        } else {
#pragma unroll
            for (int j = 0; j < 16; ++j) {
                const int d = h * HD + j * 8 + colb;
                __half2 p0 = *(__half2*)(g_Op + grow0 * DIM + d);
                __half2 p1 = *(__half2*)(g_Op + grow1 * DIM + d);
                *(__half2*)(g_Oh + grow0 * DIM + d) =
                    __floats2half2_rn(__half2float(p0.x) + O[j][0] * inv0,
                                      __half2float(p0.y) + O[j][1] * inv0);
                *(__half2*)(g_Oh + grow1 * DIM + d) =
                    __floats2half2_rn(__half2float(p1.x) + O[j][2] * inv1,
                                      __half2float(p1.y) + O[j][3] * inv1);
            }
        }
    }
}

// ---------------- launch ----------------
extern "C" void kernel_launch(void* const* d_in, const int* in_sizes, int n_in,
                              void* d_out, int out_size) {
    const float* x       = (const float*)d_in[0];
    const float* context = (const float*)d_in[1];
    const float* Wq  = (const float*)d_in[3];
    const float* bq  = (const float*)d_in[4];
    const float* Wk  = (const float*)d_in[5];
    const float* bk  = (const float*)d_in[6];
    const float* Wv  = (const float*)d_in[7];
    const float* bv  = (const float*)d_in[8];
    const float* Wak = (const float*)d_in[9];
    const float* bak = (const float*)d_in[10];
    const float* Wav = (const float*)d_in[11];
    const float* bav = (const float*)d_in[12];
    const float* Wo  = (const float*)d_in[13];
    const float* bo  = (const float*)d_in[14];
    const float* gq  = (const float*)d_in[15];
    const float* gk  = (const float*)d_in[16];
    const float* gak = (const float*)d_in[17];
    float* out = (float*)d_out;

    float *Qp, *Kp, *Vp, *Kip, *Vip;
    h16 *xh, *cth, *cih, *Oh, *WqT, *WkT, *WvT, *WakT, *WavT, *WoT;
    h16 *Qh, *Kh, *Vh, *Kih, *Vih;
    cudaGetSymbolAddress((void**)&Qp, g_Q);
    cudaGetSymbolAddress((void**)&Kp, g_K);
    cudaGetSymbolAddress((void**)&Vp, g_V);
    cudaGetSymbolAddress((void**)&Kip, g_Ki);
    cudaGetSymbolAddress((void**)&Vip, g_Vi);
    cudaGetSymbolAddress((void**)&xh, g_xh);
    cudaGetSymbolAddress((void**)&cth, g_cth);
    cudaGetSymbolAddress((void**)&cih, g_cih);
    cudaGetSymbolAddress((void**)&Oh, g_Oh);
    cudaGetSymbolAddress((void**)&WqT, g_WqT);
    cudaGetSymbolAddress((void**)&WkT, g_WkT);
    cudaGetSymbolAddress((void**)&WvT, g_WvT);
    cudaGetSymbolAddress((void**)&WakT, g_WakT);
    cudaGetSymbolAddress((void**)&WavT, g_WavT);
    cudaGetSymbolAddress((void**)&WoT, g_WoT);
    cudaGetSymbolAddress((void**)&Qh, g_Qh);
    cudaGetSymbolAddress((void**)&Kh, g_Kh);
    cudaGetSymbolAddress((void**)&Vh, g_Vh);
    cudaGetSymbolAddress((void**)&Kih, g_Kih);
    cudaGetSymbolAddress((void**)&Vih, g_Vih);

    const float* ctx_img = context;
    const float* ctx_txt = context + (long)IMG * DIM;

    static cudaStream_t s1 = nullptr, s2 = nullptr;
    static cudaEvent_t evFork = nullptr, evKV = nullptr, evA = nullptr, evS1 = nullptr;
    if (s1 == nullptr) {
        cudaStreamCreateWithFlags(&s1, cudaStreamNonBlocking);
        cudaStreamCreateWithFlags(&s2, cudaStreamNonBlocking);
        cudaEventCreateWithFlags(&evFork, cudaEventDisableTiming);
        cudaEventCreateWithFlags(&evKV, cudaEventDisableTiming);
        cudaEventCreateWithFlags(&evA, cudaEventDisableTiming);
        cudaEventCreateWithFlags(&evS1, cudaEventDisableTiming);
    }

    // log2(e) folded into the softmax scale; softmax runs in base-2 domain
    const float scale = 0.12753102245150477f;  // (1/sqrt(128)) * log2(e)
    const int gemm_smem = NSTAGE * STAGE_B;
    cudaFuncSetAttribute(gemm_mma_f16, cudaFuncAttributeMaxDynamicSharedMemorySize, gemm_smem);
    const int attn_smem = 128 * AST + 2 * KVST;
    cudaFuncSetAttribute(attn_mma, cudaFuncAttributeMaxDynamicSharedMemorySize, attn_smem);

    // ---- fork ----
    cudaEventRecord(evFork, 0);
    cudaStreamWaitEvent(s1, evFork, 0);
    cudaStreamWaitEvent(s2, evFork, 0);

    // s2: KV chain (HMMA) + Wo prep
    tohalf_pad<<<TXT, 256, 0, s2>>>(ctx_txt, cth, TXT);
    tohalf_pad<<<IMGG, 256, 0, s2>>>(ctx_img, cih, IMG);
    WTJobs wj;
    wj.W[0] = Wk;  wj.O[0] = WkT;
    wj.W[1] = Wv;  wj.O[1] = WvT;
    wj.W[2] = Wak; wj.O[2] = WakT;
    wj.W[3] = Wav; wj.O[3] = WavT;
    wj.W[4] = Wo;  wj.O[4] = WoT;
    wTb_kernel<<<dim3(DIM / 32, DIM / 32, 5), dim3(32, 8), 0, s2>>>(wj);
    gemm_mma_f16<<<dim3(DIM / 128, TXT / 128), 256, gemm_smem, s2>>>(cth, WkT, bk, Kp);
    gemm_mma_f16<<<dim3(DIM / 128, TXT / 128), 256, gemm_smem, s2>>>(cth, WvT, bv, Vp);
    gemm_mma_f16<<<dim3(DIM / 128, IMGG / 128), 256, gemm_smem, s2>>>(cih, WakT, bak, Kip);
    gemm_mma_f16<<<dim3(DIM / 128, IMGG / 128), 256, gemm_smem, s2>>>(cih, WavT, bav, Vip);
    rmsnorm_single<<<TXT, 256, 0, s2>>>(Kp, gk, 1.f, Kh, TXT);
    rmsnorm_single<<<IMGP, 256, 0, s2>>>(Kip, gak, 1.f, Kih, IMG);
    tohalf_pad<<<TXT, 256, 0, s2>>>(Vp, Vh, TXT);
    tohalf_pad<<<IMGP, 256, 0, s2>>>(Vip, Vih, IMG);
    cudaEventRecord(evKV, s2);

    // main: input conversions + Q projection half 0
    long n4 = (long)NQ * DIM / 4;
    tohalf_flat<<<(unsigned)((n4 + 255) / 256), 256>>>(x, xh, n4);
    wT_kernel<<<dim3(DIM / 32, DIM / 32), dim3(32, 8)>>>(Wq, WqT);
    gemm_mma_f16<<<dim3(DIM / 128, HALF / 128), 256, gemm_smem>>>(xh, WqT, bq, Qp);
    cudaEventRecord(evA, 0);

    // s1: half-0 tail — rmsnorm(h0) -> attn(h0) -> outproj(h0)
    cudaStreamWaitEvent(s1, evA, 0);
    rmsnorm_single<<<HALF, 256, 0, s1>>>(Qp, gq, scale, Qh, HALF);
    cudaStreamWaitEvent(s1, evKV, 0);
    attn_mma<<<dim3(HALF / 128, HEADS), 256, attn_smem, s1>>>(0);
    gemm_mma_f16<<<dim3(DIM / 128, HALF / 128), 256, gemm_smem, s1>>>(Oh, WoT, bo, out);
    cudaEventRecord(evS1, s1);

    // main: half-1 chain
    gemm_mma_f16<<<dim3(DIM / 128, HALF / 128), 256, gemm_smem>>>(
        xh + (long)HALF * DIM, WqT, bq, Qp + (long)HALF * DIM);
    rmsnorm_single<<<HALF, 256>>>(Qp + (long)HALF * DIM, gq, scale, Qh + (long)HALF * DIM, HALF);
    cudaStreamWaitEvent(0, evKV, 0);
    attn_mma<<<dim3(HALF / 128, HEADS), 256, attn_smem>>>(HALF / 128);
    gemm_mma_f16<<<dim3(DIM / 128, HALF / 128), 256, gemm_smem>>>(
        Oh + (long)HALF * DIM, WoT, bo, out + (long)HALF * DIM);

    // join
    cudaStreamWaitEvent(0, evS1, 0);
}

// round 16
// speedup vs baseline: 1.1596x; 1.1146x over previous
#include <cuda_runtime.h>
#include <cuda_fp16.h>
#include <cstdint>

#define DIM 1536
#define HEADS 12
#define HD 128
#define NQ 16384
#define HALF (NQ / 2)
#define IMG 257
#define TXT 512
#define IMGP 320   // img rows padded for attention tiles
#define IMGG 384   // img rows padded for 128-row GEMM tiles

typedef __half h16;

// ---------------- scratch (no allocations allowed) ----------------
__device__ float g_Q[(long)NQ * DIM];
__device__ float g_K[(long)TXT * DIM];
__device__ float g_V[(long)TXT * DIM];
__device__ float g_Ki[(long)IMGG * DIM];
__device__ float g_Vi[(long)IMGG * DIM];
__device__ h16 g_Op[(long)NQ * DIM];          // attention partial (txt segment), fp16
__device__ h16 g_xh[(long)NQ * DIM];
__device__ h16 g_cth[(long)TXT * DIM];        // ctx_txt fp16
__device__ h16 g_cih[(long)IMGG * DIM];       // ctx_img fp16 (zero-padded)
__device__ h16 g_Qh[(long)NQ * DIM];
__device__ h16 g_Oh[(long)NQ * DIM];
__device__ h16 g_Kh[(long)TXT * DIM];
__device__ h16 g_Vh[(long)TXT * DIM];
__device__ h16 g_Kih[(long)IMGP * DIM];
__device__ h16 g_Vih[(long)IMGP * DIM];
__device__ h16 g_WqT[(long)DIM * DIM];
__device__ h16 g_WkT[(long)DIM * DIM];
__device__ h16 g_WvT[(long)DIM * DIM];
__device__ h16 g_WakT[(long)DIM * DIM];
__device__ h16 g_WavT[(long)DIM * DIM];
__device__ h16 g_WoT[(long)DIM * DIM];

// ---------------- PTX helpers ----------------
__device__ __forceinline__ uint32_t s2u(const void* p) {
    return (uint32_t)__cvta_generic_to_shared(p);
}
__device__ __forceinline__ void cp16(uint32_t s, const void* g) {
    asm volatile("cp.async.cg.shared.global [%0], [%1], 16;\n" :: "r"(s), "l"(g) : "memory");
}
__device__ __forceinline__ void cp_commit() {
    asm volatile("cp.async.commit_group;\n" ::: "memory");
}
template <int N>
__device__ __forceinline__ void cp_wait() {
    asm volatile("cp.async.wait_group %0;\n" :: "n"(N) : "memory");
}
__device__ __forceinline__ void ldsm4(uint32_t* r, uint32_t a) {
    asm volatile("ldmatrix.sync.aligned.m8n8.x4.shared.b16 {%0,%1,%2,%3}, [%4];"
                 : "=r"(r[0]), "=r"(r[1]), "=r"(r[2]), "=r"(r[3]) : "r"(a));
}
__device__ __forceinline__ void ldsm4t(uint32_t* r, uint32_t a) {
    asm volatile("ldmatrix.sync.aligned.m8n8.x4.trans.shared.b16 {%0,%1,%2,%3}, [%4];"
                 : "=r"(r[0]), "=r"(r[1]), "=r"(r[2]), "=r"(r[3]) : "r"(a));
}
__device__ __forceinline__ void mma16816(float* c, const uint32_t* a, const uint32_t* b) {
    asm volatile(
        "mma.sync.aligned.m16n8k16.row.col.f32.f16.f16.f32 "
        "{%0,%1,%2,%3}, {%4,%5,%6,%7}, {%8,%9}, {%0,%1,%2,%3};"
        : "+f"(c[0]), "+f"(c[1]), "+f"(c[2]), "+f"(c[3])
        : "r"(a[0]), "r"(a[1]), "r"(a[2]), "r"(a[3]), "r"(b[0]), "r"(b[1]));
}
__device__ __forceinline__ uint32_t packh(float a, float b) {
    __half2 t = __floats2half2_rn(a, b);
    return *(uint32_t*)&t;
}
__device__ __forceinline__ float ex2(float x) {
    float y;
    asm("ex2.approx.ftz.f32 %0, %1;" : "=f"(y) : "f"(x));
    return y;
}

// ---------------- single-pass fp16 HMMA GEMM core ----------------
#define GSTRIDE 80
#define TILE_B (128 * GSTRIDE)
#define STAGE_B (2 * TILE_B)   // A, B
#define NSTAGE 5

__device__ __forceinline__ void gemm_body(const h16* __restrict__ A, const h16* __restrict__ BT,
                                          const float* __restrict__ bias, float* __restrict__ C,
                                          int m0, int n0, uint32_t smem0) {
    const int tid = threadIdx.x;
    const int lane = tid & 31;
    const int wid = tid >> 5;
    const int wm = wid & 3;
    const int wn = wid >> 2;

    const h16* srcs[2] = {A, BT};
    const int bases[2] = {m0, n0};

    auto load_stage = [&](int slot, int k0) {
        const uint32_t sb = smem0 + slot * STAGE_B;
#pragma unroll
        for (int t = 0; t < 4; ++t) {
            const int ch = tid + t * 256;      // 1024 chunks
            const int tile = ch >> 9;
            const int idx = ch & 511;
            const int row = idx >> 2;
            const int cb = idx & 3;
            const uint32_t so = sb + tile * TILE_B + row * GSTRIDE + cb * 16;
            const h16* g = srcs[tile] + (size_t)(bases[tile] + row) * DIM + k0 + cb * 8;
            cp16(so, g);
        }
        cp_commit();
    };

    for (int s = 0; s < NSTAGE; ++s) load_stage(s, s * 32);

    float acc[2][8][4];
#pragma unroll
    for (int mi = 0; mi < 2; ++mi)
#pragma unroll
        for (int nj = 0; nj < 8; ++nj)
#pragma unroll
            for (int r = 0; r < 4; ++r) acc[mi][nj][r] = 0.f;

    const int rowA = wm * 32 + (lane & 15);
    const int acol = (lane >> 4) * 16;
    const int rowB = wn * 64 + (lane >> 4) * 8 + (lane & 7);
    const int bcol = ((lane >> 3) & 1) * 16;

    constexpr int NKC = DIM / 32;
    for (int i = 0; i < NKC; ++i) {
        const int slot = i % NSTAGE;
        const uint32_t sb = smem0 + slot * STAGE_B;
        cp_wait<NSTAGE - 1>();
        __syncthreads();

        const uint32_t aA = sb + rowA * GSTRIDE + acol;
        const uint32_t aB = sb + TILE_B + rowB * GSTRIDE + bcol;

#pragma unroll
        for (int k16 = 0; k16 < 2; ++k16) {
            const uint32_t ko = k16 * 32;
            uint32_t ah[2][4], bh[4][4];
#pragma unroll
            for (int mi = 0; mi < 2; ++mi)
                ldsm4(ah[mi], aA + mi * 16 * GSTRIDE + ko);
#pragma unroll
            for (int ni = 0; ni < 4; ++ni)
                ldsm4(bh[ni], aB + ni * 16 * GSTRIDE + ko);
#pragma unroll
            for (int mi = 0; mi < 2; ++mi)
#pragma unroll
                for (int nj = 0; nj < 8; ++nj)
                    mma16816(acc[mi][nj], ah[mi], &bh[nj >> 1][(nj & 1) * 2]);
        }
        __syncthreads();
        if (i + NSTAGE < NKC) load_stage(slot, (i + NSTAGE) * 32);
        else cp_commit();
    }

    const int crow0 = m0 + wm * 32 + (lane >> 2);
    const int ccol0 = n0 + wn * 64 + (lane & 3) * 2;
#pragma unroll
    for (int nj = 0; nj < 8; ++nj) {
        const int col = ccol0 + nj * 8;
        const float b0 = bias[col], b1 = bias[col + 1];
#pragma unroll
        for (int mi = 0; mi < 2; ++mi) {
            float* c0 = C + (size_t)(crow0 + mi * 16) * DIM + col;
            float* c1 = c0 + 8 * DIM;
            *(float2*)c0 = make_float2(acc[mi][nj][0] + b0, acc[mi][nj][1] + b1);
            *(float2*)c1 = make_float2(acc[mi][nj][2] + b0, acc[mi][nj][3] + b1);
        }
    }
}

__global__ __launch_bounds__(256, 2)
void gemm_mma_f16(const h16* __restrict__ A, const h16* __restrict__ BT,
                  const float* __restrict__ bias, float* __restrict__ C) {
    extern __shared__ char dynsm[];
    gemm_body(A, BT, bias, C, blockIdx.y * 128, blockIdx.x * 128, s2u(dynsm));
}

// batched variant: 4 jobs selected by blockIdx.z, early-return beyond each job's tile count
struct GJobs {
    const h16* A[4];
    const h16* B[4];
    const float* bias[4];
    float* C[4];
    int MT[4];  // number of 128-row tiles
};

__global__ __launch_bounds__(256, 2)
void gemm_mma_f16_batch(GJobs jobs) {
    extern __shared__ char dynsm[];
    const int z = blockIdx.z;
    if ((int)blockIdx.y >= jobs.MT[z]) return;
    gemm_body(jobs.A[z], jobs.B[z], jobs.bias[z], jobs.C[z],
              blockIdx.y * 128, blockIdx.x * 128, s2u(dynsm));
}

// ---------------- flat fp32 -> fp16 convert ----------------
__global__ __launch_bounds__(256)
void tohalf_flat(const float* __restrict__ X, h16* __restrict__ H, long n4) {
    long i = ((long)blockIdx.x * 256 + threadIdx.x);
    if (i >= n4) return;
    float4 v = *((const float4*)X + i);
    __half2* Hp = (__half2*)H + i * 2;
    Hp[0] = __floats2half2_rn(v.x, v.y);
    Hp[1] = __floats2half2_rn(v.z, v.w);
}

// ---------------- transpose weights to single fp16 (batched) ----------------
struct WTJobs {
    const float* W[5];
    h16* O[5];
};

__global__ __launch_bounds__(256)
void wTb_kernel(WTJobs jobs) {
    const int z = blockIdx.z;
    const float* W = jobs.W[z];
    h16* Ht = jobs.O[z];
    __shared__ float t[32][33];
    const int k0 = blockIdx.y * 32, n0 = blockIdx.x * 32;
    const int tx = threadIdx.x, ty = threadIdx.y;
#pragma unroll
    for (int j = 0; j < 4; ++j)
        t[ty + j * 8][tx] = W[(size_t)(k0 + ty + j * 8) * DIM + n0 + tx];
    __syncthreads();
#pragma unroll
    for (int j = 0; j < 4; ++j)
        Ht[(size_t)(n0 + ty + j * 8) * DIM + k0 + tx] = __float2half(t[tx][ty + j * 8]);
}

__global__ __launch_bounds__(256)
void wT_kernel(const float* __restrict__ W, h16* __restrict__ Ht) {
    __shared__ float t[32][33];
    const int k0 = blockIdx.y * 32, n0 = blockIdx.x * 32;
    const int tx = threadIdx.x, ty = threadIdx.y;
#pragma unroll
    for (int j = 0; j < 4; ++j)
        t[ty + j * 8][tx] = W[(size_t)(k0 + ty + j * 8) * DIM + n0 + tx];
    __syncthreads();
#pragma unroll
    for (int j = 0; j < 4; ++j)
        Ht[(size_t)(n0 + ty + j * 8) * DIM + k0 + tx] = __float2half(t[tx][ty + j * 8]);
}

// ---------------- RMSNorm -> single fp16 (optional scale), zero-pad ----------------
__global__ __launch_bounds__(256)
void rmsnorm_single(const float* __restrict__ X, const float* __restrict__ g, float scale,
                    h16* __restrict__ H, int nvalid) {
    const int r = blockIdx.x;
    const int tid = threadIdx.x;
    if (r >= nvalid) {
#pragma unroll
        for (int i = 0; i < 6; ++i)
            H[(long)r * DIM + tid + i * 256] = __float2half(0.f);
        return;
    }
    const float* x = X + (long)r * DIM;
    float v[6];
    float ss = 0.f;
#pragma unroll
    for (int i = 0; i < 6; ++i) {
        v[i] = x[tid + i * 256];
        ss += v[i] * v[i];
    }
#pragma unroll
    for (int off = 16; off >= 1; off >>= 1)
        ss += __shfl_xor_sync(0xffffffffu, ss, off);
    __shared__ float red[8];
    if ((tid & 31) == 0) red[tid >> 5] = ss;
    __syncthreads();
    float tot = 0.f;
#pragma unroll
    for (int i = 0; i < 8; ++i) tot += red[i];
    const float rms = rsqrtf(tot * (1.f / (float)DIM) + 1e-6f);
#pragma unroll
    for (int i = 0; i < 6; ++i)
        H[(long)r * DIM + tid + i * 256] = __float2half(v[i] * rms * g[tid + i * 256] * scale);
}

// ---------------- fp16 (single) row convert with zero-pad ----------------
__global__ __launch_bounds__(256)
void tohalf_pad(const float* __restrict__ X, h16* __restrict__ H, int nvalid) {
    const int r = blockIdx.x;
    const int tid = threadIdx.x;
#pragma unroll
    for (int i = 0; i < 6; ++i) {
        float val = (r < nvalid) ? X[(long)r * DIM + tid + i * 256] : 0.f;
        H[(long)r * DIM + tid + i * 256] = __float2half(val);
    }
}

// ---------------- HMMA flash attention ----------------
#define AST 272            // smem row stride bytes (128 fp16 + 16B pad)
#define KVROW (64 * AST)
#define KVST (2 * KVROW)   // Kh, Vh per stage

__global__ __launch_bounds__(256, 2)
void attn_mma(int qb0) {
    extern __shared__ char smem[];
    const uint32_t sQh = s2u(smem);
    const uint32_t sKV = sQh + 128 * AST;   // 2 stages of KVST

    const int tid = threadIdx.x, lane = tid & 31, wid = tid >> 5;
    const int qb = blockIdx.x + qb0, h = blockIdx.y;
    const long qrow0 = (long)qb * 128;

    // Q load (its own commit group)
    {
        const h16* Qhg = g_Qh + qrow0 * DIM + h * HD;
#pragma unroll
        for (int t = 0; t < 8; ++t) {
            int c = tid + t * 256;
            int r = c >> 4, cb = c & 15;
            cp16(sQh + r * AST + cb * 16, Qhg + (long)r * DIM + cb * 8);
        }
        cp_commit();
    }

    const uint32_t qoff = (uint32_t)((wid * 16 + (lane & 15)) * AST + (lane >> 4) * 16);
    const uint32_t koff = (uint32_t)((((lane >> 4) << 3) + (lane & 7)) * AST + ((lane >> 3) & 1) * 16);
    const uint32_t voff = (uint32_t)(((((lane >> 3) & 1) << 3) + (lane & 7)) * AST + (lane >> 4) * 16);

    const int r0 = lane >> 2;
    const int colb = (lane & 3) * 2;

#pragma unroll 1
    for (int seg = 0; seg < 2; ++seg) {
        const h16 *Khg, *Vhg;
        int len, ntiles;
        if (seg == 0) {
            Khg = g_Kh; Vhg = g_Vh;
            len = TXT; ntiles = TXT / 64;
        } else {
            Khg = g_Kih; Vhg = g_Vih;
            len = IMG; ntiles = IMGP / 64;
        }

        auto load_kv = [&](int stage, int t) {
            const uint32_t sb = sKV + stage * KVST;
            const long kvbase = (long)t * 64 * DIM + h * HD;
            const h16* arrs[2] = {Khg, Vhg};
#pragma unroll
            for (int tt = 0; tt < 8; ++tt) {
                int c = tid + tt * 256;       // 2048 chunks
                int arr = c >> 10;
                int idx = c & 1023;
                int r = idx >> 4, cb = idx & 15;
                cp16(sb + arr * KVROW + r * AST + cb * 16,
                     arrs[arr] + kvbase + (long)r * DIM + cb * 8);
            }
            cp_commit();
        };

        load_kv(0, 0);  // prologue

        float mrow0 = -1e30f, mrow1 = -1e30f, lsum0 = 0.f, lsum1 = 0.f;
        float O[16][4];
#pragma unroll
        for (int j = 0; j < 16; ++j)
#pragma unroll
            for (int e = 0; e < 4; ++e) O[j][e] = 0.f;

#pragma unroll 1
        for (int t = 0; t < ntiles; ++t) {
            __syncthreads();
            if (t + 1 < ntiles) {
                load_kv((t + 1) & 1, t + 1);
                cp_wait<1>();
            } else {
                cp_wait<0>();
            }
            __syncthreads();

            const uint32_t sb = sKV + (t & 1) * KVST;
            const uint32_t sKh_ = sb, sVh_ = sb + KVROW;

            // ---- S = Q K^T (single fp16 pass, log2-domain logits) ----
            float S[8][4];
#pragma unroll
            for (int j = 0; j < 8; ++j)
#pragma unroll
                for (int e = 0; e < 4; ++e) S[j][e] = 0.f;
#pragma unroll
            for (int k16 = 0; k16 < 8; ++k16) {
                uint32_t ah[4];
                ldsm4(ah, sQh + qoff + k16 * 32);
#pragma unroll
                for (int nt2 = 0; nt2 < 4; ++nt2) {
                    uint32_t bh[4];
                    ldsm4(bh, sKh_ + koff + nt2 * 16 * AST + k16 * 32);
                    mma16816(S[2 * nt2], ah, bh);
                    mma16816(S[2 * nt2 + 1], ah, bh + 2);
                }
            }

            // ---- online softmax (base-2) ----
            const int t0 = t * 64;
            if (t0 + 64 > len) {
#pragma unroll
                for (int j = 0; j < 8; ++j) {
#pragma unroll
                    for (int e = 0; e < 2; ++e) {
                        if (t0 + j * 8 + colb + e >= len) {
                            S[j][e] = -1e30f;
                            S[j][2 + e] = -1e30f;
                        }
                    }
                }
            }
            float mx0 = -1e30f, mx1 = -1e30f;
#pragma unroll
            for (int j = 0; j < 8; ++j) {
                mx0 = fmaxf(mx0, fmaxf(S[j][0], S[j][1]));
                mx1 = fmaxf(mx1, fmaxf(S[j][2], S[j][3]));
            }
            mx0 = fmaxf(mx0, __shfl_xor_sync(0xffffffffu, mx0, 1));
            mx0 = fmaxf(mx0, __shfl_xor_sync(0xffffffffu, mx0, 2));
            mx1 = fmaxf(mx1, __shfl_xor_sync(0xffffffffu, mx1, 1));
            mx1 = fmaxf(mx1, __shfl_xor_sync(0xffffffffu, mx1, 2));
            const float nm0 = fmaxf(mrow0, mx0);
            const float nm1 = fmaxf(mrow1, mx1);
            const float sc0 = ex2(mrow0 - nm0);
            const float sc1 = ex2(mrow1 - nm1);
            mrow0 = nm0; mrow1 = nm1;

            uint32_t Ph[8][2];
            float rs0 = 0.f, rs1 = 0.f;
#pragma unroll
            for (int j = 0; j < 8; ++j) {
                float p0 = ex2(S[j][0] - nm0);
                float p1 = ex2(S[j][1] - nm0);
                float p2 = ex2(S[j][2] - nm1);
                float p3 = ex2(S[j][3] - nm1);
                rs0 += p0 + p1;
                rs1 += p2 + p3;
                Ph[j][0] = packh(p0, p1);
                Ph[j][1] = packh(p2, p3);
            }
            rs0 += __shfl_xor_sync(0xffffffffu, rs0, 1);
            rs0 += __shfl_xor_sync(0xffffffffu, rs0, 2);
            rs1 += __shfl_xor_sync(0xffffffffu, rs1, 1);
            rs1 += __shfl_xor_sync(0xffffffffu, rs1, 2);
            lsum0 = lsum0 * sc0 + rs0;
            lsum1 = lsum1 * sc1 + rs1;
#pragma unroll
            for (int j = 0; j < 16; ++j) {
                O[j][0] *= sc0; O[j][1] *= sc0;
                O[j][2] *= sc1; O[j][3] *= sc1;
            }

            // ---- O += P V (single pass) ----
#pragma unroll
            for (int s = 0; s < 4; ++s) {
                uint32_t pah[4] = {Ph[2 * s][0], Ph[2 * s][1], Ph[2 * s + 1][0], Ph[2 * s + 1][1]};
#pragma unroll
                for (int d2 = 0; d2 < 8; ++d2) {
                    uint32_t vh[4];
                    ldsm4t(vh, sVh_ + voff + s * 16 * AST + d2 * 32);
                    mma16816(O[2 * d2], pah, vh);
                    mma16816(O[2 * d2 + 1], pah, vh + 2);
                }
            }
        }

        const float inv0 = 1.f / lsum0;
        const float inv1 = 1.f / lsum1;
        const long grow0 = qrow0 + wid * 16 + r0;
        const long grow1 = grow0 + 8;
        if (seg == 0) {
#pragma unroll
            for (int j = 0; j < 16; ++j) {
                const int d = h * HD + j * 8 + colb;
                *(__half2*)(g_Op + grow0 * DIM + d) =
                    __floats2half2_rn(O[j][0] * inv0, O[j][1] * inv0);
                *(__half2*)(g_Op + grow1 * DIM + d) =
                    __floats2half2_rn(O[j][2] * inv1, O[j][3] * inv1);
            }
        } else {
#pragma unroll
            for (int j = 0; j < 16; ++j) {
                const int d = h * HD + j * 8 + colb;
                __half2 p0 = *(__half2*)(g_Op + grow0 * DIM + d);
                __half2 p1 = *(__half2*)(g_Op + grow1 * DIM + d);
                *(__half2*)(g_Oh + grow0 * DIM + d) =
                    __floats2half2_rn(__half2float(p0.x) + O[j][0] * inv0,
                                      __half2float(p0.y) + O[j][1] * inv0);
                *(__half2*)(g_Oh + grow1 * DIM + d) =
                    __floats2half2_rn(__half2float(p1.x) + O[j][2] * inv1,
                                      __half2float(p1.y) + O[j][3] * inv1);
            }
        }
    }
}

// ---------------- launch ----------------
extern "C" void kernel_launch(void* const* d_in, const int* in_sizes, int n_in,
                              void* d_out, int out_size) {
    const float* x       = (const float*)d_in[0];
    const float* context = (const float*)d_in[1];
    const float* Wq  = (const float*)d_in[3];
    const float* bq  = (const float*)d_in[4];
    const float* Wk  = (const float*)d_in[5];
    const float* bk  = (const float*)d_in[6];
    const float* Wv  = (const float*)d_in[7];
    const float* bv  = (const float*)d_in[8];
    const float* Wak = (const float*)d_in[9];
    const float* bak = (const float*)d_in[10];
    const float* Wav = (const float*)d_in[11];
    const float* bav = (const float*)d_in[12];
    const float* Wo  = (const float*)d_in[13];
    const float* bo  = (const float*)d_in[14];
    const float* gq  = (const float*)d_in[15];
    const float* gk  = (const float*)d_in[16];
    const float* gak = (const float*)d_in[17];
    float* out = (float*)d_out;

    float *Qp, *Kp, *Vp, *Kip, *Vip;
    h16 *xh, *cth, *cih, *Oh, *WqT, *WkT, *WvT, *WakT, *WavT, *WoT;
    h16 *Qh, *Kh, *Vh, *Kih, *Vih;
    cudaGetSymbolAddress((void**)&Qp, g_Q);
    cudaGetSymbolAddress((void**)&Kp, g_K);
    cudaGetSymbolAddress((void**)&Vp, g_V);
    cudaGetSymbolAddress((void**)&Kip, g_Ki);
    cudaGetSymbolAddress((void**)&Vip, g_Vi);
    cudaGetSymbolAddress((void**)&xh, g_xh);
    cudaGetSymbolAddress((void**)&cth, g_cth);
    cudaGetSymbolAddress((void**)&cih, g_cih);
    cudaGetSymbolAddress((void**)&Oh, g_Oh);
    cudaGetSymbolAddress((void**)&WqT, g_WqT);
    cudaGetSymbolAddress((void**)&WkT, g_WkT);
    cudaGetSymbolAddress((void**)&WvT, g_WvT);
    cudaGetSymbolAddress((void**)&WakT, g_WakT);
    cudaGetSymbolAddress((void**)&WavT, g_WavT);
    cudaGetSymbolAddress((void**)&WoT, g_WoT);
    cudaGetSymbolAddress((void**)&Qh, g_Qh);
    cudaGetSymbolAddress((void**)&Kh, g_Kh);
    cudaGetSymbolAddress((void**)&Vh, g_Vh);
    cudaGetSymbolAddress((void**)&Kih, g_Kih);
    cudaGetSymbolAddress((void**)&Vih, g_Vih);

    const float* ctx_img = context;
    const float* ctx_txt = context + (long)IMG * DIM;

    static cudaStream_t s1 = nullptr, s2 = nullptr;
    static cudaEvent_t evFork = nullptr, evKV = nullptr, evA = nullptr, evS1 = nullptr, evWq = nullptr;
    if (s1 == nullptr) {
        cudaStreamCreateWithFlags(&s1, cudaStreamNonBlocking);
        cudaStreamCreateWithFlags(&s2, cudaStreamNonBlocking);
        cudaEventCreateWithFlags(&evFork, cudaEventDisableTiming);
        cudaEventCreateWithFlags(&evKV, cudaEventDisableTiming);
        cudaEventCreateWithFlags(&evA, cudaEventDisableTiming);
        cudaEventCreateWithFlags(&evS1, cudaEventDisableTiming);
        cudaEventCreateWithFlags(&evWq, cudaEventDisableTiming);
    }

    // log2(e) folded into the softmax scale; softmax runs in base-2 domain
    const float scale = 0.12753102245150477f;  // (1/sqrt(128)) * log2(e)
    const int gemm_smem = NSTAGE * STAGE_B;
    cudaFuncSetAttribute(gemm_mma_f16, cudaFuncAttributeMaxDynamicSharedMemorySize, gemm_smem);
    cudaFuncSetAttribute(gemm_mma_f16_batch, cudaFuncAttributeMaxDynamicSharedMemorySize, gemm_smem);
    const int attn_smem = 128 * AST + 2 * KVST;
    cudaFuncSetAttribute(attn_mma, cudaFuncAttributeMaxDynamicSharedMemorySize, attn_smem);

    // ---- fork ----
    cudaEventRecord(evFork, 0);
    cudaStreamWaitEvent(s1, evFork, 0);
    cudaStreamWaitEvent(s2, evFork, 0);

    // s1: Wq transpose (parallel with x conversion on main)
    wT_kernel<<<dim3(DIM / 32, DIM / 32), dim3(32, 8), 0, s1>>>(Wq, WqT);
    cudaEventRecord(evWq, s1);

    // s2: KV chain (batched HMMA) + Wo prep
    tohalf_pad<<<TXT, 256, 0, s2>>>(ctx_txt, cth, TXT);
    tohalf_pad<<<IMGG, 256, 0, s2>>>(ctx_img, cih, IMG);
    WTJobs wj;
    wj.W[0] = Wk;  wj.O[0] = WkT;
    wj.W[1] = Wv;  wj.O[1] = WvT;
    wj.W[2] = Wak; wj.O[2] = WakT;
    wj.W[3] = Wav; wj.O[3] = WavT;
    wj.W[4] = Wo;  wj.O[4] = WoT;
    wTb_kernel<<<dim3(DIM / 32, DIM / 32, 5), dim3(32, 8), 0, s2>>>(wj);
    GJobs gj;
    gj.A[0] = cth; gj.B[0] = WkT;  gj.bias[0] = bk;  gj.C[0] = Kp;  gj.MT[0] = TXT / 128;
    gj.A[1] = cth; gj.B[1] = WvT;  gj.bias[1] = bv;  gj.C[1] = Vp;  gj.MT[1] = TXT / 128;
    gj.A[2] = cih; gj.B[2] = WakT; gj.bias[2] = bak; gj.C[2] = Kip; gj.MT[2] = IMGG / 128;
    gj.A[3] = cih; gj.B[3] = WavT; gj.bias[3] = bav; gj.C[3] = Vip; gj.MT[3] = IMGG / 128;
    gemm_mma_f16_batch<<<dim3(DIM / 128, TXT / 128, 4), 256, gemm_smem, s2>>>(gj);
    rmsnorm_single<<<TXT, 256, 0, s2>>>(Kp, gk, 1.f, Kh, TXT);
    rmsnorm_single<<<IMGP, 256, 0, s2>>>(Kip, gak, 1.f, Kih, IMG);
    tohalf_pad<<<TXT, 256, 0, s2>>>(Vp, Vh, TXT);
    tohalf_pad<<<IMGP, 256, 0, s2>>>(Vip, Vih, IMG);
    cudaEventRecord(evKV, s2);

    // main: convert x half 0, then Q projection half 0
    long n4h = (long)HALF * DIM / 4;
    tohalf_flat<<<(unsigned)((n4h + 255) / 256), 256>>>(x, xh, n4h);
    cudaStreamWaitEvent(0, evWq, 0);
    gemm_mma_f16<<<dim3(DIM / 128, HALF / 128), 256, gemm_smem>>>(xh, WqT, bq, Qp);
    cudaEventRecord(evA, 0);

    // s1: half-0 tail — rmsnorm(h0) -> attn(h0) -> outproj(h0)
    cudaStreamWaitEvent(s1, evA, 0);
    rmsnorm_single<<<HALF, 256, 0, s1>>>(Qp, gq, scale, Qh, HALF);
    cudaStreamWaitEvent(s1, evKV, 0);
    attn_mma<<<dim3(HALF / 128, HEADS), 256, attn_smem, s1>>>(0);
    gemm_mma_f16<<<dim3(DIM / 128, HALF / 128), 256, gemm_smem, s1>>>(Oh, WoT, bo, out);
    cudaEventRecord(evS1, s1);

    // main: half-1 chain
    tohalf_flat<<<(unsigned)((n4h + 255) / 256), 256>>>(
        x + (long)HALF * DIM, xh + (long)HALF * DIM, n4h);
    gemm_mma_f16<<<dim3(DIM / 128, HALF / 128), 256, gemm_smem>>>(
        xh + (long)HALF * DIM, WqT, bq, Qp + (long)HALF * DIM);
    rmsnorm_single<<<HALF, 256>>>(Qp + (long)HALF * DIM, gq, scale, Qh + (long)HALF * DIM, HALF);
    cudaStreamWaitEvent(0, evKV, 0);
    attn_mma<<<dim3(HALF / 128, HEADS), 256, attn_smem>>>(HALF / 128);
    gemm_mma_f16<<<dim3(DIM / 128, HALF / 128), 256, gemm_smem>>>(
        Oh + (long)HALF * DIM, WoT, bo, out + (long)HALF * DIM);

    // join
    cudaStreamWaitEvent(0, evS1, 0);
}